// round 11
// baseline (speedup 1.0000x reference)
#include <cuda_runtime.h>
#include <cuda_bf16.h>
#include <math.h>
#include <stdint.h>

typedef unsigned short ushortt;

#define Bn 4
#define Ln 128
#define Cn 6
#define BL 512
#define KC1P 528
#define KFP 1056
#define KFULL 1042

#define O_EB    0
#define O_WIHF  (O_EB + 204800)
#define O_WIHB  (O_WIHF + 409600)
#define O_PRE   (O_WIHB + 409600)
#define O_CTX   (O_PRE + 1048576)
#define O_CTXB  (O_CTX + 262144)
#define O_WQB   (O_CTXB + 262144)
#define O_WKB   (O_WQB + 262144)
#define O_Q     (O_WKB + 262144)
#define O_K     (O_Q + 262144)
#define O_CTX2  (O_K + 262144)
#define O_F     (O_CTX2 + 262144)
#define O_G     (O_F + 3072)
#define O_F2    (O_G + 3072)
#define O_G2    (O_F2 + 3072)
#define O_U     (O_G2 + 3072)
#define O_V     (O_U + 524288)
#define O_U2    (O_V + 524288)
#define O_V2    (O_U2 + 524288)
#define O_ABUB  (O_V2 + 524288)
#define O_ABVB  (O_ABUB + 270336)
#define O_WUCB  (O_ABVB + 270336)
#define O_WVCB  (O_WUCB + 540672)
#define O_WPB   (O_WVCB + 540672)
#define O_UBB   (O_WPB + 1081344)
#define O_VBB   (O_UBB + 540672)
#define SCRATCH_TOTAL (O_VBB + 540672)
__device__ __align__(256) float d_scratch[SCRATCH_TOTAL];

static __device__ __forceinline__ uint32_t smem_u32(const void* p) {
    uint32_t a;
    asm("{ .reg .u64 t; cvta.to.shared.u64 t, %1; cvt.u32.u64 %0, t; }" : "=r"(a) : "l"(p));
    return a;
}
static __device__ __forceinline__ void bsplit(float v, ushortt& h, ushortt& l) {
    __nv_bfloat16 hb = __float2bfloat16_rn(v);
    __nv_bfloat16 lb = __float2bfloat16_rn(v - __bfloat162float(hb));
    h = __bfloat16_as_ushort(hb);
    l = __bfloat16_as_ushort(lb);
}
static __device__ __forceinline__ float fsig(float x) {
    return __fdividef(1.f, 1.f + __expf(-x));
}
static __device__ __forceinline__ float ftanh(float x) {
    return 1.f - __fdividef(2.f, __expf(2.f * x) + 1.f);
}
#define LDSM4(R, a) asm volatile("ldmatrix.sync.aligned.m8n8.x4.shared.b16 {%0,%1,%2,%3}, [%4];" \
    : "=r"((R)[0]), "=r"((R)[1]), "=r"((R)[2]), "=r"((R)[3]) : "r"(a))
#define MMA(c, a, b0, b1) asm volatile( \
    "mma.sync.aligned.m16n8k16.row.col.f32.bf16.bf16.f32 {%0,%1,%2,%3},{%4,%5,%6,%7},{%8,%9},{%0,%1,%2,%3};" \
    : "+f"((c)[0]), "+f"((c)[1]), "+f"((c)[2]), "+f"((c)[3]) \
    : "r"((a)[0]), "r"((a)[1]), "r"((a)[2]), "r"((a)[3]), "r"(b0), "r"(b1))
#define FMA2(acc, a, b) asm("fma.rn.f32x2 %0, %1, %2, %0;" : "+l"(acc) : "l"(a), "l"(b))

// ---- bf16 hi/lo tensor-core GEMM (64x64 tiles, 128 thr) ----
__global__ __launch_bounds__(128)
void bgemm(const ushortt* __restrict__ A0, const ushortt* __restrict__ A1, int lda,
           const ushortt* __restrict__ W0, const ushortt* __restrict__ W1, int ldw,
           const float* bx0, const float* by0, const float* bx1, const float* by1,
           float* C0, float* C1, int ldc, int K)
{
    __shared__ __align__(16) ushortt sm[2][4][1536];
    const int z = blockIdx.z;
    const ushortt* A = z ? A1 : A0;
    const ushortt* W = z ? W1 : W0;
    const float* bx = z ? bx1 : bx0;
    const float* by = z ? by1 : by0;
    float* C = z ? C1 : C0;
    const int m0 = blockIdx.y * 64, n0 = blockIdx.x * 64;
    const int Mt = gridDim.y * 64, Nt = gridDim.x * 64;
    const ushortt* Ah = A + (size_t)m0 * lda;
    const ushortt* Al = Ah + (size_t)Mt * lda;
    const ushortt* Wh = W + (size_t)n0 * ldw;
    const ushortt* Wl = Wh + (size_t)Nt * ldw;
    const int tid = threadIdx.x, w = tid >> 5, L = tid & 31;
    const int wm = (w & 1) * 32, wn = (w >> 1) * 32;
    const uint32_t sb = smem_u32(sm);
    const int r = (L & 7) + ((L >> 3) & 1) * 8, ko = ((L >> 4) & 1) * 16;
    const uint32_t oA0 = (uint32_t)((wm + r) * 48 + ko), oA1 = (uint32_t)((wm + 16 + r) * 48 + ko);
    const int br = (L & 7) + ((L >> 4) & 1) * 8, bko = ((L >> 3) & 1) * 16;
    const uint32_t oB0 = (uint32_t)((wn + br) * 48 + bko), oB1 = (uint32_t)((wn + 16 + br) * 48 + bko);
    const int row = tid >> 1, hf = tid & 1;

    float c[2][4][4];
#pragma unroll
    for (int i = 0; i < 2; i++)
#pragma unroll
        for (int j = 0; j < 4; j++)
#pragma unroll
            for (int q = 0; q < 4; q++) c[i][j][q] = 0.f;

    const int T = K >> 4;
    uint4 va, vl, vwh, vwl;
#define GLD(k0) do { \
    va  = *(const uint4*)(Ah + (size_t)row * lda + (k0) + hf * 8); \
    vl  = *(const uint4*)(Al + (size_t)row * lda + (k0) + hf * 8); \
    vwh = *(const uint4*)(Wh + (size_t)row * ldw + (k0) + hf * 8); \
    vwl = *(const uint4*)(Wl + (size_t)row * ldw + (k0) + hf * 8); } while (0)
#define SST(buf) do { \
    char* bp = (char*)sm + (buf) * 12288 + row * 48 + hf * 16; \
    *(uint4*)bp = va; *(uint4*)(bp + 3072) = vl; \
    *(uint4*)(bp + 6144) = vwh; *(uint4*)(bp + 9216) = vwl; } while (0)

    GLD(0);
    SST(0);
    __syncthreads();
    for (int t = 0; t < T; t++) {
        if (t + 1 < T) GLD((t + 1) << 4);
        {
            uint32_t base = sb + (uint32_t)((t & 1) * 12288);
            uint32_t ah[2][4], alr[2][4], bh[2][4], bl[2][4];
            LDSM4(ah[0], base + oA0);
            LDSM4(ah[1], base + oA1);
            LDSM4(alr[0], base + 3072 + oA0);
            LDSM4(alr[1], base + 3072 + oA1);
            LDSM4(bh[0], base + 6144 + oB0);
            LDSM4(bh[1], base + 6144 + oB1);
            LDSM4(bl[0], base + 9216 + oB0);
            LDSM4(bl[1], base + 9216 + oB1);
#pragma unroll
            for (int mf = 0; mf < 2; mf++)
#pragma unroll
                for (int nf = 0; nf < 4; nf++) {
                    int g = nf >> 1, o = (nf & 1) * 2;
                    MMA(c[mf][nf], ah[mf], bh[g][o], bh[g][o + 1]);
                    MMA(c[mf][nf], ah[mf], bl[g][o], bl[g][o + 1]);
                    MMA(c[mf][nf], alr[mf], bh[g][o], bh[g][o + 1]);
                }
        }
        if (t + 1 < T) SST((t + 1) & 1);
        __syncthreads();
    }
    const int g2 = L >> 2, qc = (L & 3) * 2;
#pragma unroll
    for (int nf = 0; nf < 4; nf++) {
        int col = n0 + wn + nf * 8 + qc;
        float b0 = 0.f, b1 = 0.f;
        if (bx) { b0 += bx[col]; b1 += bx[col + 1]; }
        if (by) { b0 += by[col]; b1 += by[col + 1]; }
#pragma unroll
        for (int mf = 0; mf < 2; mf++) {
            int rw = m0 + wm + mf * 16 + g2;
            *(float2*)(C + (size_t)rw * ldc + col) = make_float2(c[mf][nf][0] + b0, c[mf][nf][1] + b1);
            *(float2*)(C + (size_t)(rw + 8) * ldc + col) = make_float2(c[mf][nf][2] + b0, c[mf][nf][3] + b1);
        }
    }
}

// ---- fused weight prep + embedding ----
#define PN0 (BL * 400)
#define PN1 (1024 * 400)
#define PN3 (512 * 512)
#define PN5 (1024 * KC1P)
#define PN6 (1024 * KFP)
#define N_PREP (PN0 + 2 * PN1 + 2 * PN3 + PN5 + PN6)
__global__ void prep_w(const int* __restrict__ toks, const float* __restrict__ mask,
                       const float* __restrict__ gen, const float* __restrict__ dom,
                       const float* __restrict__ wf, const float* __restrict__ wb,
                       const float* __restrict__ wq, const float* __restrict__ wk,
                       const float* __restrict__ fw, ushortt* EB,
                       ushortt* WIHF, ushortt* WIHB, ushortt* WQB, ushortt* WKB,
                       ushortt* WUC, ushortt* WVC, ushortt* WP) {
    int idx = blockIdx.x * blockDim.x + threadIdx.x;
    ushortt h, l;
    if (idx < PN0) {
        int rowi = idx / 400, j = idx % 400;
        int tok = toks[rowi];
        float v = ((j < 300) ? gen[tok * 300 + j] : dom[tok * 100 + (j - 300)]) * mask[rowi];
        bsplit(v, h, l);
        EB[idx] = h; EB[PN0 + idx] = l;
        return;
    }
    idx -= PN0;
    if (idx < PN1) { bsplit(wf[idx], h, l); WIHF[idx] = h; WIHF[PN1 + idx] = l; return; }
    idx -= PN1;
    if (idx < PN1) { bsplit(wb[idx], h, l); WIHB[idx] = h; WIHB[PN1 + idx] = l; return; }
    idx -= PN1;
    if (idx < PN3) { bsplit(wq[idx], h, l); WQB[idx] = h; WQB[PN3 + idx] = l; return; }
    idx -= PN3;
    if (idx < PN3) { bsplit(wk[idx], h, l); WKB[idx] = h; WKB[PN3 + idx] = l; return; }
    idx -= PN3;
    if (idx < PN5) {
        int nn = idx / KC1P, j = idx % KC1P;
        float u = 0.f, v = 0.f;
        if (j < 524) {
            int sU = (j < 512) ? j : ((j < 518) ? 1024 + (j - 512) : 1036 + (j - 518));
            int sV = (j < 512) ? 512 + j : ((j < 518) ? 1030 + (j - 512) : 1036 + (j - 518));
            u = fw[(size_t)nn * KFULL + sU];
            v = fw[(size_t)nn * KFULL + sV];
        }
        bsplit(u, h, l); WUC[idx] = h; WUC[PN5 + idx] = l;
        bsplit(v, h, l); WVC[idx] = h; WVC[PN5 + idx] = l;
        return;
    }
    idx -= PN5;
    if (idx < PN6) {
        int nn = idx / KFP, j = idx % KFP;
        float v = (j < KFULL) ? fw[(size_t)nn * KFULL + j] : 0.f;
        bsplit(v, h, l);
        WP[idx] = h;
        WP[PN6 + idx] = l;
    }
}

// ---- BiLSTM: 8-CTA clusters, single-poller mbarrier signaling ----
__global__ __launch_bounds__(256, 1) __cluster_dims__(8, 1, 1)
void lstm_cluster(const float* __restrict__ whh_f, const float* __restrict__ whh_b,
                  const float* __restrict__ pre, float* __restrict__ ctx,
                  ushortt* __restrict__ ctxb) {
    __shared__ float hb[2][264];
    __shared__ __align__(8) unsigned long long mbars[2];
    const int tid = threadIdx.x;
    unsigned rank;
    asm("mov.u32 %0, %%cluster_ctarank;" : "=r"(rank));
    const int cid = blockIdx.x >> 3, dir = cid >> 2, batch = cid & 3;
    const int ct = (int)rank * 256 + tid;
    const int half = ct & 1, p = ct >> 1, gate = p & 3, d = p >> 2;
    const int gbase = (tid & 31) & ~7;
    const int lane7 = tid & 7;
    const bool prod = (tid & 7) == 0;
    const int dslot = (d < 128) ? d : d + 4;
    const float* whh = dir ? whh_b : whh_f;
    ulonglong2 w2[32];
    const ulonglong2* wp = (const ulonglong2*)(whh + ((size_t)(gate * 256 + d)) * 256 + half * 128);
#pragma unroll
    for (int i = 0; i < 32; i++) w2[i] = wp[i];
    for (int j = tid; j < 264; j += 256) hb[0][j] = 0.f;
    uint32_t mb0 = smem_u32(&mbars[0]);
    uint32_t mb1 = smem_u32(&mbars[1]);
    if (tid == 0) {
        asm volatile("mbarrier.init.shared.b64 [%0], %1;" :: "r"(mb0), "r"(8u) : "memory");
        asm volatile("mbarrier.init.shared.b64 [%0], %1;" :: "r"(mb1), "r"(8u) : "memory");
    }
    const float* preB = pre + ((size_t)dir * 512 + batch * 128) * 1024 + gate * 256 + d;
    float* ctxB = ctx + ((size_t)batch * 128) * 512 + dir * 256 + d;
    ushortt* cbB = ctxb + ((size_t)batch * 128) * 512 + dir * 256 + d;
    uint32_t la0 = smem_u32(&hb[0][dslot]);
    uint32_t la1 = smem_u32(&hb[1][dslot]);
    asm volatile("barrier.cluster.arrive.aligned;" ::: "memory");
    asm volatile("barrier.cluster.wait.aligned;" ::: "memory");
    float preCur = preB[(size_t)(dir ? 127 : 0) * 1024];
    float cc = 0.f;
    for (int s = 0; s < 128; s++) {
        if (s > 0) {
            if (tid == 0) {
                uint32_t mba = (s & 1) ? mb1 : mb0;
                uint32_t par = (uint32_t)(((s - 1) >> 1) & 1);
                asm volatile("{\n\t.reg .pred P;\n\tW%=:\n\t"
                    "mbarrier.try_wait.parity.acquire.cluster.shared::cta.b64 P, [%0], %1;\n\t"
                    "@P bra D%=;\n\tbra W%=;\n\tD%=:\n\t}" :: "r"(mba), "r"(par) : "memory");
            }
            __syncthreads();
        }
        const ulonglong2* hp = (const ulonglong2*)(&hb[s & 1][half ? 132 : 0]);
        unsigned long long a0 = 0ull, a1 = 0ull, a2 = 0ull, a3 = 0ull;
#pragma unroll
        for (int i = 0; i < 32; i += 2) {
            ulonglong2 h0 = hp[i], h1 = hp[i + 1];
            FMA2(a0, w2[i].x, h0.x);
            FMA2(a1, w2[i].y, h0.y);
            FMA2(a2, w2[i + 1].x, h1.x);
            FMA2(a3, w2[i + 1].y, h1.y);
        }
        float x0, x1, y0, y1, z0, z1, u0, u1;
        asm("mov.b64 {%0, %1}, %2;" : "=f"(x0), "=f"(x1) : "l"(a0));
        asm("mov.b64 {%0, %1}, %2;" : "=f"(y0), "=f"(y1) : "l"(a1));
        asm("mov.b64 {%0, %1}, %2;" : "=f"(z0), "=f"(z1) : "l"(a2));
        asm("mov.b64 {%0, %1}, %2;" : "=f"(u0), "=f"(u1) : "l"(a3));
        float acc = ((x0 + x1) + (y0 + y1)) + ((z0 + z1) + (u0 + u1));
        acc += __shfl_xor_sync(0xffffffffu, acc, 1);
        float gv = acc + preCur;
        // parallel activations: each lane handles its own gate
        float act = (gate == 2) ? ftanh(gv) : fsig(gv);
        float aI = __shfl_sync(0xffffffffu, act, gbase);
        float aF = __shfl_sync(0xffffffffu, act, gbase + 2);
        float aG = __shfl_sync(0xffffffffu, act, gbase + 4);
        float aO = __shfl_sync(0xffffffffu, act, gbase + 6);
        float hv = 0.f;
        if (prod) {
            cc = aF * cc + aI * aG;
            hv = aO * ftanh(cc);
        }
        hv = __shfl_sync(0xffffffffu, hv, gbase);
        if (s < 127) {
            uint32_t la = ((s + 1) & 1) ? la1 : la0;
            uint32_t ra;
            asm("mapa.shared::cluster.u32 %0, %1, %2;" : "=r"(ra) : "r"(la), "r"(lane7));
            asm volatile("st.shared::cluster.f32 [%0], %1;" :: "r"(ra), "f"(hv));
            asm volatile("fence.acq_rel.cluster;" ::: "memory");
        }
        __syncthreads();
        if (s < 127 && tid == 0) {
            uint32_t mba = ((s + 1) & 1) ? mb1 : mb0;
#pragma unroll
            for (int rr = 0; rr < 8; rr++) {
                uint32_t ra;
                asm("mapa.shared::cluster.u32 %0, %1, %2;" : "=r"(ra) : "r"(mba), "r"(rr));
                asm volatile("mbarrier.arrive.release.cluster.shared::cluster.b64 _, [%0];"
                             :: "r"(ra) : "memory");
            }
        }
        int time = dir ? (127 - s) : s;
        if (prod) {
            ctxB[(size_t)time * 512] = hv;
            ushortt hh, ll;
            bsplit(hv, hh, ll);
            cbB[(size_t)time * 512] = hh;
            cbB[(size_t)(512 * 512) + (size_t)time * 512] = ll;
        }
        if (s < 127) preCur = preB[(size_t)(dir ? (126 - s) : (s + 1)) * 1024];
    }
    asm volatile("barrier.cluster.arrive.aligned;" ::: "memory");
    asm volatile("barrier.cluster.wait.aligned;" ::: "memory");
}

__global__ __launch_bounds__(256)
void attn_kernel(const float* __restrict__ q, const float* __restrict__ k,
                 const float* __restrict__ ctx, float* __restrict__ ctx2) {
    int row = blockIdx.x, b = row >> 7, tid = threadIdx.x;
    __shared__ float qsh[512], sc[128], red[128];
    for (int j = tid; j < 512; j += 256) qsh[j] = q[(size_t)row * 512 + j];
    __syncthreads();
    {
        int m = tid >> 1, half = tid & 1;
        const float* kr = k + ((size_t)(b * 128 + m)) * 512 + half * 256;
        const float* qh = qsh + half * 256;
        float s = 0.f;
#pragma unroll 8
        for (int j = 0; j < 256; j++) s = fmaf(qh[j], kr[j], s);
        s += __shfl_xor_sync(0xffffffffu, s, 1);
        if (!half) sc[m] = s;
    }
    __syncthreads();
    if (tid < 128) red[tid] = sc[tid];
    __syncthreads();
    for (int s = 64; s > 0; s >>= 1) {
        if (tid < s) red[tid] = fmaxf(red[tid], red[tid + s]);
        __syncthreads();
    }
    float mx = red[0];
    __syncthreads();
    if (tid < 128) { float e = __expf(sc[tid] - mx); sc[tid] = e; red[tid] = e; }
    __syncthreads();
    for (int s = 64; s > 0; s >>= 1) {
        if (tid < s) red[tid] += red[tid + s];
        __syncthreads();
    }
    float inv = 1.f / red[0];
    __syncthreads();
    int c0 = tid * 2;
    float o0 = 0.f, o1 = 0.f;
    for (int m = 0; m < 128; m++) {
        float a = sc[m] * inv;
        float2 cv = *(const float2*)(ctx + ((size_t)(b * 128 + m)) * 512 + c0);
        o0 = fmaf(a, cv.x, o0);
        o1 = fmaf(a, cv.y, o1);
    }
    float2 bs = *(const float2*)(ctx + (size_t)row * 512 + c0);
    *(float2*)(ctx2 + (size_t)row * 512 + c0) = make_float2(o0 + bs.x, o1 + bs.y);
}

__global__ __launch_bounds__(256)
void smallmm3(const float* __restrict__ A0, const float* __restrict__ A1, int lda, int K,
              const float* __restrict__ W, int ldw, int off0, int off1,
              const float* __restrict__ bias, float* __restrict__ C0, float* __restrict__ C1) {
    int z = blockIdx.z;
    int w = threadIdx.x >> 5, L = threadIdx.x & 31;
    int row = blockIdx.x * 8 + w;
    const float* A = (z ? A1 : A0) + (size_t)row * lda;
    int off = z ? off1 : off0;
    float acc[Cn] = {0, 0, 0, 0, 0, 0};
    for (int i = L; i * 4 < K; i += 32) {
        float4 a = *(const float4*)(A + i * 4);
#pragma unroll
        for (int c = 0; c < Cn; c++) {
            float4 wv = *(const float4*)(W + (size_t)c * ldw + off + i * 4);
            acc[c] += a.x * wv.x + a.y * wv.y + a.z * wv.z + a.w * wv.w;
        }
    }
#pragma unroll
    for (int sft = 16; sft > 0; sft >>= 1)
#pragma unroll
        for (int c = 0; c < Cn; c++) acc[c] += __shfl_xor_sync(0xffffffffu, acc[c], sft);
    if (L == 0) {
        float* C = (z ? C1 : C0) + (size_t)row * Cn;
#pragma unroll
        for (int c = 0; c < Cn; c++) C[c] = acc[c] + ((z == 0 && bias) ? bias[c] : 0.f);
    }
}

static __device__ __forceinline__ void row_lm(const float* F, const float* G,
                                              int b, int l, float* lmsh) {
    int tid = threadIdx.x;
    if (tid < 192) {
        int c = tid >> 5, lane = tid & 31;
        const float* Fb = F + (size_t)(b * Ln) * Cn + c;
        const float* Gb = G + (size_t)(b * Ln) * Cn + c;
        float pf = -3.0e38f, sg = -3.0e38f;
        for (int l2 = lane; l2 <= l; l2 += 32) pf = fmaxf(pf, Fb[l2 * Cn]);
        for (int l2 = l + lane; l2 < Ln; l2 += 32) sg = fmaxf(sg, Gb[l2 * Cn]);
#pragma unroll
        for (int sft = 16; sft > 0; sft >>= 1) {
            pf = fmaxf(pf, __shfl_xor_sync(0xffffffffu, pf, sft));
            sg = fmaxf(sg, __shfl_xor_sync(0xffffffffu, sg, sft));
        }
        if (lane == 0) {
            float v1 = Gb[l * Cn] + pf;
            if (l < Ln - 1) v1 = fmaxf(v1, 0.f);
            float v2 = Fb[l * Cn] + sg;
            if (l > 0) v2 = fmaxf(v2, 0.f);
            lmsh[c] = fmaxf(v1, v2);
        }
    }
    __syncthreads();
}

__global__ __launch_bounds__(256)
void build_ab1(const float* __restrict__ ctx2, const float* __restrict__ F,
               const float* __restrict__ G,
               ushortt* __restrict__ AbU, ushortt* __restrict__ AbV) {
    int row = blockIdx.x;
    __shared__ float lmsh[8];
    row_lm(F, G, row >> 7, row & 127, lmsh);
    const int n = BL * KC1P;
    for (int j = threadIdx.x; j < KC1P; j += blockDim.x) {
        float u = 0.f, v = 0.f;
        if (j < 512) { u = v = ctx2[(size_t)row * 512 + j]; }
        else if (j < 518) { u = v = lmsh[j - 512]; }
        else if (j < 524) { u = F[(size_t)row * Cn + (j - 518)]; v = G[(size_t)row * Cn + (j - 518)]; }
        ushortt h, l;
        int idx = row * KC1P + j;
        bsplit(u, h, l); AbU[idx] = h; AbU[n + idx] = l;
        bsplit(v, h, l); AbV[idx] = h; AbV[n + idx] = l;
    }
}

__global__ __launch_bounds__(256)
void build_bar(const float* __restrict__ U, const float* __restrict__ V,
               const float* __restrict__ F, const float* __restrict__ G,
               ushortt* __restrict__ Ub, ushortt* __restrict__ Vb) {
    int row = blockIdx.x;
    __shared__ float lmsh[8];
    row_lm(F, G, row >> 7, row & 127, lmsh);
    const int n = BL * KFP;
    for (int j = threadIdx.x; j < KFP; j += blockDim.x) {
        float u = 0.f, v = 0.f;
        if (j < 1024) { u = U[(size_t)row * 1024 + j]; v = V[(size_t)row * 1024 + j]; }
        else if (j < 1030) { u = lmsh[j - 1024]; }
        else if (j < 1036) { v = lmsh[j - 1030]; }
        else if (j < 1042) { u = F[(size_t)row * Cn + (j - 1036)]; v = G[(size_t)row * Cn + (j - 1036)]; }
        ushortt h, l;
        int idx = row * KFP + j;
        bsplit(u, h, l); Ub[idx] = h; Ub[n + idx] = l;
        bsplit(v, h, l); Vb[idx] = h; Vb[n + idx] = l;
    }
}

__global__ void final_kernel(const float* __restrict__ F, const float* __restrict__ G, float* __restrict__ out) {
    int idx = blockIdx.x * blockDim.x + threadIdx.x;
    if (idx >= Bn * Ln * Ln * Cn) return;
    int c = idx % Cn, j = (idx / Cn) % Ln, i = (idx / (Cn * Ln)) % Ln, b = idx / (Cn * Ln * Ln);
    out[idx] = F[((size_t)(b * Ln + i)) * Cn + c] + G[((size_t)(b * Ln + j)) * Cn + c];
}

extern "C" void kernel_launch(void* const* d_in, const int* in_sizes, int n_in,
                              void* d_out, int out_size) {
    (void)in_sizes; (void)n_in; (void)out_size;
    const int* toks = (const int*)d_in[0];
    const float* mask = (const float*)d_in[2];
    const float* gen = (const float*)d_in[3];
    const float* dom = (const float*)d_in[4];
    const float* wih_f = (const float*)d_in[5];
    const float* whh_f = (const float*)d_in[6];
    const float* bih_f = (const float*)d_in[7];
    const float* bhh_f = (const float*)d_in[8];
    const float* wih_b = (const float*)d_in[9];
    const float* whh_b = (const float*)d_in[10];
    const float* bih_b = (const float*)d_in[11];
    const float* bhh_b = (const float*)d_in[12];
    const float* wq = (const float*)d_in[13];
    const float* bq = (const float*)d_in[14];
    const float* wk = (const float*)d_in[15];
    const float* bk = (const float*)d_in[16];
    const float* feat_w = (const float*)d_in[17];
    const float* feat_b = (const float*)d_in[18];
    const float* cls_w = (const float*)d_in[19];
    const float* cls_b = (const float*)d_in[20];
    float* out = (float*)d_out;

    float* S = nullptr;
    cudaGetSymbolAddress((void**)&S, d_scratch);
    ushortt* EB   = (ushortt*)(S + O_EB);
    ushortt* WIHF = (ushortt*)(S + O_WIHF);
    ushortt* WIHB = (ushortt*)(S + O_WIHB);
    float* pre  = S + O_PRE;
    float* ctx  = S + O_CTX;
    ushortt* CTXB = (ushortt*)(S + O_CTXB);
    ushortt* WQB  = (ushortt*)(S + O_WQB);
    ushortt* WKB  = (ushortt*)(S + O_WKB);
    float* qb = S + O_Q;
    float* kb = S + O_K;
    float* ctx2 = S + O_CTX2;
    float* F = S + O_F;   float* G = S + O_G;
    float* F2 = S + O_F2; float* G2 = S + O_G2;
    float* U = S + O_U;   float* V = S + O_V;
    float* U2 = S + O_U2; float* V2 = S + O_V2;
    ushortt* ABUB = (ushortt*)(S + O_ABUB);
    ushortt* ABVB = (ushortt*)(S + O_ABVB);
    ushortt* WUCB = (ushortt*)(S + O_WUCB);
    ushortt* WVCB = (ushortt*)(S + O_WVCB);
    ushortt* WPB  = (ushortt*)(S + O_WPB);
    ushortt* UBB  = (ushortt*)(S + O_UBB);
    ushortt* VBB  = (ushortt*)(S + O_VBB);

    prep_w<<<(N_PREP + 255) / 256, 256>>>(toks, mask, gen, dom, wih_f, wih_b, wq, wk, feat_w,
                                          EB, WIHF, WIHB, WQB, WKB, WUCB, WVCB, WPB);
    bgemm<<<dim3(16, 8, 2), 128>>>(EB, EB, 400, WIHF, WIHB, 400,
                                   bih_f, bhh_f, bih_b, bhh_b,
                                   pre, pre + (size_t)BL * 1024, 1024, 400);
    lstm_cluster<<<64, 256>>>(whh_f, whh_b, pre, ctx, CTXB);
    bgemm<<<dim3(8, 8, 2), 128>>>(CTXB, CTXB, 512, WQB, WKB, 512,
                                  bq, nullptr, bk, nullptr, qb, kb, 512, 512);
    attn_kernel<<<BL, 256>>>(qb, kb, ctx, ctx2);
    smallmm3<<<dim3(BL / 8, 1, 2), 256>>>(ctx2, ctx2, 512, 512, cls_w, 1024, 0, 512, cls_b, F, G);
    build_ab1<<<BL, 256>>>(ctx2, F, G, ABUB, ABVB);
    bgemm<<<dim3(16, 8, 2), 128>>>(ABUB, ABVB, KC1P, WUCB, WVCB, KC1P,
                                   feat_b, nullptr, nullptr, nullptr, U, V, 1024, KC1P);
    smallmm3<<<dim3(BL / 8, 1, 2), 256>>>(U, V, 1024, 1024, cls_w, 1024, 0, 0, cls_b, F2, G2);
    build_bar<<<BL, 256>>>(U, V, F2, G2, UBB, VBB);
    bgemm<<<dim3(16, 8, 2), 128>>>(UBB, VBB, KFP, WPB, WPB, KFP,
                                   feat_b, nullptr, nullptr, nullptr, U2, V2, 1024, KFP);
    smallmm3<<<dim3(BL / 8, 1, 2), 256>>>(U2, V2, 1024, 1024, cls_w, 1024, 0, 0, cls_b, F, G);
    final_kernel<<<1536, 256>>>(F, G, out);
}

// round 13
// speedup vs baseline: 1.5329x; 1.5329x over previous
#include <cuda_runtime.h>
#include <cuda_bf16.h>
#include <math.h>
#include <stdint.h>

typedef unsigned short ushortt;

#define Bn 4
#define Ln 128
#define Cn 6
#define BL 512
#define KC1P 528
#define KFP 1056
#define KFULL 1042

#define O_EB    0
#define O_WIHF  (O_EB + 204800)
#define O_WIHB  (O_WIHF + 409600)
#define O_PRE   (O_WIHB + 409600)
#define O_CTX   (O_PRE + 1048576)
#define O_CTXB  (O_CTX + 262144)
#define O_WQB   (O_CTXB + 262144)
#define O_WKB   (O_WQB + 262144)
#define O_Q     (O_WKB + 262144)
#define O_K     (O_Q + 262144)
#define O_CTX2  (O_K + 262144)
#define O_F     (O_CTX2 + 262144)
#define O_G     (O_F + 3072)
#define O_F2    (O_G + 3072)
#define O_G2    (O_F2 + 3072)
#define O_U     (O_G2 + 3072)
#define O_V     (O_U + 524288)
#define O_U2    (O_V + 524288)
#define O_V2    (O_U2 + 524288)
#define O_ABUB  (O_V2 + 524288)
#define O_ABVB  (O_ABUB + 270336)
#define O_WUCB  (O_ABVB + 270336)
#define O_WVCB  (O_WUCB + 540672)
#define O_WPB   (O_WVCB + 540672)
#define O_UBB   (O_WPB + 1081344)
#define O_VBB   (O_UBB + 540672)
#define SCRATCH_TOTAL (O_VBB + 540672)
__device__ __align__(256) float d_scratch[SCRATCH_TOTAL];

static __device__ __forceinline__ uint32_t smem_u32(const void* p) {
    uint32_t a;
    asm("{ .reg .u64 t; cvta.to.shared.u64 t, %1; cvt.u32.u64 %0, t; }" : "=r"(a) : "l"(p));
    return a;
}
static __device__ __forceinline__ void bsplit(float v, ushortt& h, ushortt& l) {
    __nv_bfloat16 hb = __float2bfloat16_rn(v);
    __nv_bfloat16 lb = __float2bfloat16_rn(v - __bfloat162float(hb));
    h = __bfloat16_as_ushort(hb);
    l = __bfloat16_as_ushort(lb);
}
static __device__ __forceinline__ float fsig(float x) {
    return __fdividef(1.f, 1.f + __expf(-x));
}
static __device__ __forceinline__ float ftanh(float x) {
    return 1.f - __fdividef(2.f, __expf(2.f * x) + 1.f);
}
#define LDSM4(R, a) asm volatile("ldmatrix.sync.aligned.m8n8.x4.shared.b16 {%0,%1,%2,%3}, [%4];" \
    : "=r"((R)[0]), "=r"((R)[1]), "=r"((R)[2]), "=r"((R)[3]) : "r"(a))
#define MMA(c, a, b0, b1) asm volatile( \
    "mma.sync.aligned.m16n8k16.row.col.f32.bf16.bf16.f32 {%0,%1,%2,%3},{%4,%5,%6,%7},{%8,%9},{%0,%1,%2,%3};" \
    : "+f"((c)[0]), "+f"((c)[1]), "+f"((c)[2]), "+f"((c)[3]) \
    : "r"((a)[0]), "r"((a)[1]), "r"((a)[2]), "r"((a)[3]), "r"(b0), "r"(b1))
#define FMA2(acc, a, b) asm("fma.rn.f32x2 %0, %1, %2, %0;" : "+l"(acc) : "l"(a), "l"(b))
#define CPA(dst, src) asm volatile("cp.async.cg.shared.global [%0], [%1], 16;" \
    :: "r"(dst), "l"(src) : "memory")
#define CPA_COMMIT() asm volatile("cp.async.commit_group;" ::: "memory")
#define CPA_WAIT2() asm volatile("cp.async.wait_group 2;" ::: "memory")

// ---- bf16 hi/lo tensor-core GEMM (64x64 tiles, 128 thr), 3-stage cp.async ----
__global__ __launch_bounds__(128)
void bgemm(const ushortt* __restrict__ A0, const ushortt* __restrict__ A1, int lda,
           const ushortt* __restrict__ W0, const ushortt* __restrict__ W1, int ldw,
           const float* bx0, const float* by0, const float* bx1, const float* by1,
           float* C0, float* C1, int ldc, int K)
{
    __shared__ __align__(16) ushortt sm[3][4][1536];
    const int z = blockIdx.z;
    const ushortt* A = z ? A1 : A0;
    const ushortt* W = z ? W1 : W0;
    const float* bx = z ? bx1 : bx0;
    const float* by = z ? by1 : by0;
    float* C = z ? C1 : C0;
    const int m0 = blockIdx.y * 64, n0 = blockIdx.x * 64;
    const int Mt = gridDim.y * 64, Nt = gridDim.x * 64;
    const ushortt* Ah = A + (size_t)m0 * lda;
    const ushortt* Al = Ah + (size_t)Mt * lda;
    const ushortt* Wh = W + (size_t)n0 * ldw;
    const ushortt* Wl = Wh + (size_t)Nt * ldw;
    const int tid = threadIdx.x, w = tid >> 5, L = tid & 31;
    const int wm = (w & 1) * 32, wn = (w >> 1) * 32;
    const uint32_t sb = smem_u32(sm);
    const int r = (L & 7) + ((L >> 3) & 1) * 8, ko = ((L >> 4) & 1) * 16;
    const uint32_t oA0 = (uint32_t)((wm + r) * 48 + ko), oA1 = (uint32_t)((wm + 16 + r) * 48 + ko);
    const int br = (L & 7) + ((L >> 4) & 1) * 8, bko = ((L >> 3) & 1) * 16;
    const uint32_t oB0 = (uint32_t)((wn + br) * 48 + bko), oB1 = (uint32_t)((wn + 16 + br) * 48 + bko);
    const int row = tid >> 1, hf = tid & 1;

    float c[2][4][4];
#pragma unroll
    for (int i = 0; i < 2; i++)
#pragma unroll
        for (int j = 0; j < 4; j++)
#pragma unroll
            for (int q = 0; q < 4; q++) c[i][j][q] = 0.f;

    const int T = K >> 4;
    const uint32_t dbase = sb + (uint32_t)(row * 48 + hf * 16);
    const size_t goffA = (size_t)row * lda + hf * 8;
    const size_t goffW = (size_t)row * ldw + hf * 8;

#define ISSUE(stg, k0) do { \
    uint32_t bp = dbase + (uint32_t)(stg) * 12288u; \
    CPA(bp,        (const void*)(Ah + goffA + (k0))); \
    CPA(bp + 3072, (const void*)(Al + goffA + (k0))); \
    CPA(bp + 6144, (const void*)(Wh + goffW + (k0))); \
    CPA(bp + 9216, (const void*)(Wl + goffW + (k0))); } while (0)

    ISSUE(0, 0);
    CPA_COMMIT();
    ISSUE(1, 16);
    CPA_COMMIT();

    for (int t = 0; t < T; t++) {
        if (t + 2 < T) ISSUE((t + 2) % 3, (t + 2) << 4);
        CPA_COMMIT();
        CPA_WAIT2();
        __syncthreads();
        {
            uint32_t base = sb + (uint32_t)((t % 3) * 12288);
            uint32_t ah[2][4], alr[2][4], bh[2][4], bl[2][4];
            LDSM4(ah[0], base + oA0);
            LDSM4(ah[1], base + oA1);
            LDSM4(alr[0], base + 3072 + oA0);
            LDSM4(alr[1], base + 3072 + oA1);
            LDSM4(bh[0], base + 6144 + oB0);
            LDSM4(bh[1], base + 6144 + oB1);
            LDSM4(bl[0], base + 9216 + oB0);
            LDSM4(bl[1], base + 9216 + oB1);
#pragma unroll
            for (int mf = 0; mf < 2; mf++)
#pragma unroll
                for (int nf = 0; nf < 4; nf++) {
                    int g = nf >> 1, o = (nf & 1) * 2;
                    MMA(c[mf][nf], ah[mf], bh[g][o], bh[g][o + 1]);
                    MMA(c[mf][nf], ah[mf], bl[g][o], bl[g][o + 1]);
                    MMA(c[mf][nf], alr[mf], bh[g][o], bh[g][o + 1]);
                }
        }
        __syncthreads();
    }
    const int g2 = L >> 2, qc = (L & 3) * 2;
#pragma unroll
    for (int nf = 0; nf < 4; nf++) {
        int col = n0 + wn + nf * 8 + qc;
        float b0 = 0.f, b1 = 0.f;
        if (bx) { b0 += bx[col]; b1 += bx[col + 1]; }
        if (by) { b0 += by[col]; b1 += by[col + 1]; }
#pragma unroll
        for (int mf = 0; mf < 2; mf++) {
            int rw = m0 + wm + mf * 16 + g2;
            *(float2*)(C + (size_t)rw * ldc + col) = make_float2(c[mf][nf][0] + b0, c[mf][nf][1] + b1);
            *(float2*)(C + (size_t)(rw + 8) * ldc + col) = make_float2(c[mf][nf][2] + b0, c[mf][nf][3] + b1);
        }
    }
}

// ---- fused weight prep + embedding ----
#define PN0 (BL * 400)
#define PN1 (1024 * 400)
#define PN3 (512 * 512)
#define PN5 (1024 * KC1P)
#define PN6 (1024 * KFP)
#define N_PREP (PN0 + 2 * PN1 + 2 * PN3 + PN5 + PN6)
__global__ void prep_w(const int* __restrict__ toks, const float* __restrict__ mask,
                       const float* __restrict__ gen, const float* __restrict__ dom,
                       const float* __restrict__ wf, const float* __restrict__ wb,
                       const float* __restrict__ wq, const float* __restrict__ wk,
                       const float* __restrict__ fw, ushortt* EB,
                       ushortt* WIHF, ushortt* WIHB, ushortt* WQB, ushortt* WKB,
                       ushortt* WUC, ushortt* WVC, ushortt* WP) {
    int idx = blockIdx.x * blockDim.x + threadIdx.x;
    ushortt h, l;
    if (idx < PN0) {
        int rowi = idx / 400, j = idx % 400;
        int tok = toks[rowi];
        float v = ((j < 300) ? gen[tok * 300 + j] : dom[tok * 100 + (j - 300)]) * mask[rowi];
        bsplit(v, h, l);
        EB[idx] = h; EB[PN0 + idx] = l;
        return;
    }
    idx -= PN0;
    if (idx < PN1) { bsplit(wf[idx], h, l); WIHF[idx] = h; WIHF[PN1 + idx] = l; return; }
    idx -= PN1;
    if (idx < PN1) { bsplit(wb[idx], h, l); WIHB[idx] = h; WIHB[PN1 + idx] = l; return; }
    idx -= PN1;
    if (idx < PN3) { bsplit(wq[idx], h, l); WQB[idx] = h; WQB[PN3 + idx] = l; return; }
    idx -= PN3;
    if (idx < PN3) { bsplit(wk[idx], h, l); WKB[idx] = h; WKB[PN3 + idx] = l; return; }
    idx -= PN3;
    if (idx < PN5) {
        int nn = idx / KC1P, j = idx % KC1P;
        float u = 0.f, v = 0.f;
        if (j < 524) {
            int sU = (j < 512) ? j : ((j < 518) ? 1024 + (j - 512) : 1036 + (j - 518));
            int sV = (j < 512) ? 512 + j : ((j < 518) ? 1030 + (j - 512) : 1036 + (j - 518));
            u = fw[(size_t)nn * KFULL + sU];
            v = fw[(size_t)nn * KFULL + sV];
        }
        bsplit(u, h, l); WUC[idx] = h; WUC[PN5 + idx] = l;
        bsplit(v, h, l); WVC[idx] = h; WVC[PN5 + idx] = l;
        return;
    }
    idx -= PN5;
    if (idx < PN6) {
        int nn = idx / KFP, j = idx % KFP;
        float v = (j < KFULL) ? fw[(size_t)nn * KFULL + j] : 0.f;
        bsplit(v, h, l);
        WP[idx] = h;
        WP[PN6 + idx] = l;
    }
}

// ---- BiLSTM: 8-CTA clusters, barrier.cluster per step (proven fastest sync) ----
__global__ __launch_bounds__(256, 1) __cluster_dims__(8, 1, 1)
void lstm_cluster(const float* __restrict__ whh_f, const float* __restrict__ whh_b,
                  const float* __restrict__ pre, float* __restrict__ ctx,
                  ushortt* __restrict__ ctxb) {
    __shared__ float hb[2][264];
    const int tid = threadIdx.x;
    unsigned rank;
    asm("mov.u32 %0, %%cluster_ctarank;" : "=r"(rank));
    const int cid = blockIdx.x >> 3, dir = cid >> 2, batch = cid & 3;
    const int ct = (int)rank * 256 + tid;
    const int half = ct & 1, p = ct >> 1, gate = p & 3, d = p >> 2;
    const int gbase = (tid & 31) & ~7;
    const int lane7 = tid & 7;
    const bool prod = (tid & 7) == 0;
    const int dslot = (d < 128) ? d : d + 4;
    const float* whh = dir ? whh_b : whh_f;
    ulonglong2 w2[32];
    const ulonglong2* wp = (const ulonglong2*)(whh + ((size_t)(gate * 256 + d)) * 256 + half * 128);
#pragma unroll
    for (int i = 0; i < 32; i++) w2[i] = wp[i];
    for (int j = tid; j < 264; j += 256) hb[0][j] = 0.f;
    const float* preB = pre + ((size_t)dir * 512 + batch * 128) * 1024 + gate * 256 + d;
    float* ctxB = ctx + ((size_t)batch * 128) * 512 + dir * 256 + d;
    ushortt* cbB = ctxb + ((size_t)batch * 128) * 512 + dir * 256 + d;
    uint32_t la0 = smem_u32(&hb[0][dslot]);
    uint32_t la1 = smem_u32(&hb[1][dslot]);
    asm volatile("barrier.cluster.arrive.aligned;" ::: "memory");
    float preCur = preB[(size_t)(dir ? 127 : 0) * 1024];
    float cc = 0.f;
    for (int s = 0; s < 128; s++) {
        asm volatile("barrier.cluster.wait.aligned;" ::: "memory");
        const ulonglong2* hp = (const ulonglong2*)(&hb[s & 1][half ? 132 : 0]);
        unsigned long long a0 = 0ull, a1 = 0ull, a2 = 0ull, a3 = 0ull;
#pragma unroll
        for (int i = 0; i < 32; i += 2) {
            ulonglong2 h0 = hp[i], h1 = hp[i + 1];
            FMA2(a0, w2[i].x, h0.x);
            FMA2(a1, w2[i].y, h0.y);
            FMA2(a2, w2[i + 1].x, h1.x);
            FMA2(a3, w2[i + 1].y, h1.y);
        }
        float x0, x1, y0, y1, z0, z1, u0, u1;
        asm("mov.b64 {%0, %1}, %2;" : "=f"(x0), "=f"(x1) : "l"(a0));
        asm("mov.b64 {%0, %1}, %2;" : "=f"(y0), "=f"(y1) : "l"(a1));
        asm("mov.b64 {%0, %1}, %2;" : "=f"(z0), "=f"(z1) : "l"(a2));
        asm("mov.b64 {%0, %1}, %2;" : "=f"(u0), "=f"(u1) : "l"(a3));
        float acc = ((x0 + x1) + (y0 + y1)) + ((z0 + z1) + (u0 + u1));
        acc += __shfl_xor_sync(0xffffffffu, acc, 1);
        float gv = acc + preCur;
        float act = (gate == 2) ? ftanh(gv) : fsig(gv);
        float aI = __shfl_sync(0xffffffffu, act, gbase);
        float aF = __shfl_sync(0xffffffffu, act, gbase + 2);
        float aG = __shfl_sync(0xffffffffu, act, gbase + 4);
        float aO = __shfl_sync(0xffffffffu, act, gbase + 6);
        float hv = 0.f;
        if (prod) {
            cc = aF * cc + aI * aG;
            hv = aO * ftanh(cc);
        }
        hv = __shfl_sync(0xffffffffu, hv, gbase);
        if (s < 127) {
            uint32_t la = ((s + 1) & 1) ? la1 : la0;
            uint32_t ra;
            asm("mapa.shared::cluster.u32 %0, %1, %2;" : "=r"(ra) : "r"(la), "r"(lane7));
            asm volatile("st.shared::cluster.f32 [%0], %1;" :: "r"(ra), "f"(hv));
        }
        asm volatile("barrier.cluster.arrive.aligned;" ::: "memory");
        int time = dir ? (127 - s) : s;
        if (prod) {
            ctxB[(size_t)time * 512] = hv;
            ushortt hh, ll;
            bsplit(hv, hh, ll);
            cbB[(size_t)time * 512] = hh;
            cbB[(size_t)(512 * 512) + (size_t)time * 512] = ll;
        }
        if (s < 127) preCur = preB[(size_t)(dir ? (126 - s) : (s + 1)) * 1024];
    }
    asm volatile("barrier.cluster.wait.aligned;" ::: "memory");
}

__global__ __launch_bounds__(256)
void attn_kernel(const float* __restrict__ q, const float* __restrict__ k,
                 const float* __restrict__ ctx, float* __restrict__ ctx2) {
    int row = blockIdx.x, b = row >> 7, tid = threadIdx.x;
    __shared__ float qsh[512], sc[128], red[128];
    for (int j = tid; j < 512; j += 256) qsh[j] = q[(size_t)row * 512 + j];
    __syncthreads();
    {
        int m = tid >> 1, half = tid & 1;
        const float* kr = k + ((size_t)(b * 128 + m)) * 512 + half * 256;
        const float* qh = qsh + half * 256;
        float s = 0.f;
#pragma unroll 8
        for (int j = 0; j < 256; j++) s = fmaf(qh[j], kr[j], s);
        s += __shfl_xor_sync(0xffffffffu, s, 1);
        if (!half) sc[m] = s;
    }
    __syncthreads();
    if (tid < 128) red[tid] = sc[tid];
    __syncthreads();
    for (int s = 64; s > 0; s >>= 1) {
        if (tid < s) red[tid] = fmaxf(red[tid], red[tid + s]);
        __syncthreads();
    }
    float mx = red[0];
    __syncthreads();
    if (tid < 128) { float e = __expf(sc[tid] - mx); sc[tid] = e; red[tid] = e; }
    __syncthreads();
    for (int s = 64; s > 0; s >>= 1) {
        if (tid < s) red[tid] += red[tid + s];
        __syncthreads();
    }
    float inv = 1.f / red[0];
    __syncthreads();
    int c0 = tid * 2;
    float o0 = 0.f, o1 = 0.f;
    for (int m = 0; m < 128; m++) {
        float a = sc[m] * inv;
        float2 cv = *(const float2*)(ctx + ((size_t)(b * 128 + m)) * 512 + c0);
        o0 = fmaf(a, cv.x, o0);
        o1 = fmaf(a, cv.y, o1);
    }
    float2 bs = *(const float2*)(ctx + (size_t)row * 512 + c0);
    *(float2*)(ctx2 + (size_t)row * 512 + c0) = make_float2(o0 + bs.x, o1 + bs.y);
}

__global__ __launch_bounds__(256)
void smallmm3(const float* __restrict__ A0, const float* __restrict__ A1, int lda, int K,
              const float* __restrict__ W, int ldw, int off0, int off1,
              const float* __restrict__ bias, float* __restrict__ C0, float* __restrict__ C1) {
    int z = blockIdx.z;
    int w = threadIdx.x >> 5, L = threadIdx.x & 31;
    int row = blockIdx.x * 8 + w;
    const float* A = (z ? A1 : A0) + (size_t)row * lda;
    int off = z ? off1 : off0;
    float acc[Cn] = {0, 0, 0, 0, 0, 0};
    for (int i = L; i * 4 < K; i += 32) {
        float4 a = *(const float4*)(A + i * 4);
#pragma unroll
        for (int c = 0; c < Cn; c++) {
            float4 wv = *(const float4*)(W + (size_t)c * ldw + off + i * 4);
            acc[c] += a.x * wv.x + a.y * wv.y + a.z * wv.z + a.w * wv.w;
        }
    }
#pragma unroll
    for (int sft = 16; sft > 0; sft >>= 1)
#pragma unroll
        for (int c = 0; c < Cn; c++) acc[c] += __shfl_xor_sync(0xffffffffu, acc[c], sft);
    if (L == 0) {
        float* C = (z ? C1 : C0) + (size_t)row * Cn;
#pragma unroll
        for (int c = 0; c < Cn; c++) C[c] = acc[c] + ((z == 0 && bias) ? bias[c] : 0.f);
    }
}

static __device__ __forceinline__ void row_lm(const float* F, const float* G,
                                              int b, int l, float* lmsh) {
    int tid = threadIdx.x;
    if (tid < 192) {
        int c = tid >> 5, lane = tid & 31;
        const float* Fb = F + (size_t)(b * Ln) * Cn + c;
        const float* Gb = G + (size_t)(b * Ln) * Cn + c;
        float pf = -3.0e38f, sg = -3.0e38f;
        for (int l2 = lane; l2 <= l; l2 += 32) pf = fmaxf(pf, Fb[l2 * Cn]);
        for (int l2 = l + lane; l2 < Ln; l2 += 32) sg = fmaxf(sg, Gb[l2 * Cn]);
#pragma unroll
        for (int sft = 16; sft > 0; sft >>= 1) {
            pf = fmaxf(pf, __shfl_xor_sync(0xffffffffu, pf, sft));
            sg = fmaxf(sg, __shfl_xor_sync(0xffffffffu, sg, sft));
        }
        if (lane == 0) {
            float v1 = Gb[l * Cn] + pf;
            if (l < Ln - 1) v1 = fmaxf(v1, 0.f);
            float v2 = Fb[l * Cn] + sg;
            if (l > 0) v2 = fmaxf(v2, 0.f);
            lmsh[c] = fmaxf(v1, v2);
        }
    }
    __syncthreads();
}

__global__ __launch_bounds__(256)
void build_ab1(const float* __restrict__ ctx2, const float* __restrict__ F,
               const float* __restrict__ G,
               ushortt* __restrict__ AbU, ushortt* __restrict__ AbV) {
    int row = blockIdx.x;
    __shared__ float lmsh[8];
    row_lm(F, G, row >> 7, row & 127, lmsh);
    const int n = BL * KC1P;
    for (int j = threadIdx.x; j < KC1P; j += blockDim.x) {
        float u = 0.f, v = 0.f;
        if (j < 512) { u = v = ctx2[(size_t)row * 512 + j]; }
        else if (j < 518) { u = v = lmsh[j - 512]; }
        else if (j < 524) { u = F[(size_t)row * Cn + (j - 518)]; v = G[(size_t)row * Cn + (j - 518)]; }
        ushortt h, l;
        int idx = row * KC1P + j;
        bsplit(u, h, l); AbU[idx] = h; AbU[n + idx] = l;
        bsplit(v, h, l); AbV[idx] = h; AbV[n + idx] = l;
    }
}

__global__ __launch_bounds__(256)
void build_bar(const float* __restrict__ U, const float* __restrict__ V,
               const float* __restrict__ F, const float* __restrict__ G,
               ushortt* __restrict__ Ub, ushortt* __restrict__ Vb) {
    int row = blockIdx.x;
    __shared__ float lmsh[8];
    row_lm(F, G, row >> 7, row & 127, lmsh);
    const int n = BL * KFP;
    for (int j = threadIdx.x; j < KFP; j += blockDim.x) {
        float u = 0.f, v = 0.f;
        if (j < 1024) { u = U[(size_t)row * 1024 + j]; v = V[(size_t)row * 1024 + j]; }
        else if (j < 1030) { u = lmsh[j - 1024]; }
        else if (j < 1036) { v = lmsh[j - 1030]; }
        else if (j < 1042) { u = F[(size_t)row * Cn + (j - 1036)]; v = G[(size_t)row * Cn + (j - 1036)]; }
        ushortt h, l;
        int idx = row * KFP + j;
        bsplit(u, h, l); Ub[idx] = h; Ub[n + idx] = l;
        bsplit(v, h, l); Vb[idx] = h; Vb[n + idx] = l;
    }
}

__global__ void final_kernel(const float* __restrict__ F, const float* __restrict__ G, float* __restrict__ out) {
    int idx = blockIdx.x * blockDim.x + threadIdx.x;
    if (idx >= Bn * Ln * Ln * Cn) return;
    int c = idx % Cn, j = (idx / Cn) % Ln, i = (idx / (Cn * Ln)) % Ln, b = idx / (Cn * Ln * Ln);
    out[idx] = F[((size_t)(b * Ln + i)) * Cn + c] + G[((size_t)(b * Ln + j)) * Cn + c];
}

extern "C" void kernel_launch(void* const* d_in, const int* in_sizes, int n_in,
                              void* d_out, int out_size) {
    (void)in_sizes; (void)n_in; (void)out_size;
    const int* toks = (const int*)d_in[0];
    const float* mask = (const float*)d_in[2];
    const float* gen = (const float*)d_in[3];
    const float* dom = (const float*)d_in[4];
    const float* wih_f = (const float*)d_in[5];
    const float* whh_f = (const float*)d_in[6];
    const float* bih_f = (const float*)d_in[7];
    const float* bhh_f = (const float*)d_in[8];
    const float* wih_b = (const float*)d_in[9];
    const float* whh_b = (const float*)d_in[10];
    const float* bih_b = (const float*)d_in[11];
    const float* bhh_b = (const float*)d_in[12];
    const float* wq = (const float*)d_in[13];
    const float* bq = (const float*)d_in[14];
    const float* wk = (const float*)d_in[15];
    const float* bk = (const float*)d_in[16];
    const float* feat_w = (const float*)d_in[17];
    const float* feat_b = (const float*)d_in[18];
    const float* cls_w = (const float*)d_in[19];
    const float* cls_b = (const float*)d_in[20];
    float* out = (float*)d_out;

    float* S = nullptr;
    cudaGetSymbolAddress((void**)&S, d_scratch);
    ushortt* EB   = (ushortt*)(S + O_EB);
    ushortt* WIHF = (ushortt*)(S + O_WIHF);
    ushortt* WIHB = (ushortt*)(S + O_WIHB);
    float* pre  = S + O_PRE;
    float* ctx  = S + O_CTX;
    ushortt* CTXB = (ushortt*)(S + O_CTXB);
    ushortt* WQB  = (ushortt*)(S + O_WQB);
    ushortt* WKB  = (ushortt*)(S + O_WKB);
    float* qb = S + O_Q;
    float* kb = S + O_K;
    float* ctx2 = S + O_CTX2;
    float* F = S + O_F;   float* G = S + O_G;
    float* F2 = S + O_F2; float* G2 = S + O_G2;
    float* U = S + O_U;   float* V = S + O_V;
    float* U2 = S + O_U2; float* V2 = S + O_V2;
    ushortt* ABUB = (ushortt*)(S + O_ABUB);
    ushortt* ABVB = (ushortt*)(S + O_ABVB);
    ushortt* WUCB = (ushortt*)(S + O_WUCB);
    ushortt* WVCB = (ushortt*)(S + O_WVCB);
    ushortt* WPB  = (ushortt*)(S + O_WPB);
    ushortt* UBB  = (ushortt*)(S + O_UBB);
    ushortt* VBB  = (ushortt*)(S + O_VBB);

    prep_w<<<(N_PREP + 255) / 256, 256>>>(toks, mask, gen, dom, wih_f, wih_b, wq, wk, feat_w,
                                          EB, WIHF, WIHB, WQB, WKB, WUCB, WVCB, WPB);
    bgemm<<<dim3(16, 8, 2), 128>>>(EB, EB, 400, WIHF, WIHB, 400,
                                   bih_f, bhh_f, bih_b, bhh_b,
                                   pre, pre + (size_t)BL * 1024, 1024, 400);
    lstm_cluster<<<64, 256>>>(whh_f, whh_b, pre, ctx, CTXB);
    bgemm<<<dim3(8, 8, 2), 128>>>(CTXB, CTXB, 512, WQB, WKB, 512,
                                  bq, nullptr, bk, nullptr, qb, kb, 512, 512);
    attn_kernel<<<BL, 256>>>(qb, kb, ctx, ctx2);
    smallmm3<<<dim3(BL / 8, 1, 2), 256>>>(ctx2, ctx2, 512, 512, cls_w, 1024, 0, 512, cls_b, F, G);
    build_ab1<<<BL, 256>>>(ctx2, F, G, ABUB, ABVB);
    bgemm<<<dim3(16, 8, 2), 128>>>(ABUB, ABVB, KC1P, WUCB, WVCB, KC1P,
                                   feat_b, nullptr, nullptr, nullptr, U, V, 1024, KC1P);
    smallmm3<<<dim3(BL / 8, 1, 2), 256>>>(U, V, 1024, 1024, cls_w, 1024, 0, 0, cls_b, F2, G2);
    build_bar<<<BL, 256>>>(U, V, F2, G2, UBB, VBB);
    bgemm<<<dim3(16, 8, 2), 128>>>(UBB, VBB, KFP, WPB, WPB, KFP,
                                   feat_b, nullptr, nullptr, nullptr, U2, V2, 1024, KFP);
    smallmm3<<<dim3(BL / 8, 1, 2), 256>>>(U2, V2, 1024, 1024, cls_w, 1024, 0, 0, cls_b, F, G);
    final_kernel<<<1536, 256>>>(F, G, out);
}

// round 14
// speedup vs baseline: 1.5572x; 1.0158x over previous
#include <cuda_runtime.h>
#include <cuda_bf16.h>
#include <math.h>
#include <stdint.h>

typedef unsigned short ushortt;

#define Bn 4
#define Ln 128
#define Cn 6
#define BL 512
#define KC1P 528
#define KFP 1056
#define KFULL 1042

#define O_EB    0
#define O_WIHF  (O_EB + 204800)
#define O_WIHB  (O_WIHF + 409600)
#define O_PRE   (O_WIHB + 409600)
#define O_CTX   (O_PRE + 1048576)
#define O_CTXB  (O_CTX + 262144)
#define O_WQB   (O_CTXB + 262144)
#define O_WKB   (O_WQB + 262144)
#define O_Q     (O_WKB + 262144)
#define O_K     (O_Q + 262144)
#define O_CTX2  (O_K + 262144)
#define O_F     (O_CTX2 + 262144)
#define O_G     (O_F + 3072)
#define O_F2    (O_G + 3072)
#define O_G2    (O_F2 + 3072)
#define O_U     (O_G2 + 3072)
#define O_V     (O_U + 524288)
#define O_U2    (O_V + 524288)
#define O_V2    (O_U2 + 524288)
#define O_ABUB  (O_V2 + 524288)
#define O_ABVB  (O_ABUB + 270336)
#define O_WUCB  (O_ABVB + 270336)
#define O_WVCB  (O_WUCB + 540672)
#define O_WPB   (O_WVCB + 540672)
#define O_UBB   (O_WPB + 1081344)
#define O_VBB   (O_UBB + 540672)
#define SCRATCH_TOTAL (O_VBB + 540672)
__device__ __align__(256) float d_scratch[SCRATCH_TOTAL];

static __device__ __forceinline__ uint32_t smem_u32(const void* p) {
    uint32_t a;
    asm("{ .reg .u64 t; cvta.to.shared.u64 t, %1; cvt.u32.u64 %0, t; }" : "=r"(a) : "l"(p));
    return a;
}
static __device__ __forceinline__ void bsplit(float v, ushortt& h, ushortt& l) {
    __nv_bfloat16 hb = __float2bfloat16_rn(v);
    __nv_bfloat16 lb = __float2bfloat16_rn(v - __bfloat162float(hb));
    h = __bfloat16_as_ushort(hb);
    l = __bfloat16_as_ushort(lb);
}
static __device__ __forceinline__ float fsig(float x) {
    return __fdividef(1.f, 1.f + __expf(-x));
}
static __device__ __forceinline__ float ftanh(float x) {
    return 1.f - __fdividef(2.f, __expf(2.f * x) + 1.f);
}
#define LDSM4(R, a) asm volatile("ldmatrix.sync.aligned.m8n8.x4.shared.b16 {%0,%1,%2,%3}, [%4];" \
    : "=r"((R)[0]), "=r"((R)[1]), "=r"((R)[2]), "=r"((R)[3]) : "r"(a))
#define MMA(c, a, b0, b1) asm volatile( \
    "mma.sync.aligned.m16n8k16.row.col.f32.bf16.bf16.f32 {%0,%1,%2,%3},{%4,%5,%6,%7},{%8,%9},{%0,%1,%2,%3};" \
    : "+f"((c)[0]), "+f"((c)[1]), "+f"((c)[2]), "+f"((c)[3]) \
    : "r"((a)[0]), "r"((a)[1]), "r"((a)[2]), "r"((a)[3]), "r"(b0), "r"(b1))
#define FMA2(acc, a, b) asm("fma.rn.f32x2 %0, %1, %2, %0;" : "+l"(acc) : "l"(a), "l"(b))
#define CPA(dst, src) asm volatile("cp.async.cg.shared.global [%0], [%1], 16;" \
    :: "r"(dst), "l"(src) : "memory")
#define CPA_COMMIT() asm volatile("cp.async.commit_group;" ::: "memory")
#define CPA_WAIT3() asm volatile("cp.async.wait_group 3;" ::: "memory")

// ---- bf16 hi/lo tensor-core GEMM (64x64 tiles, 128 thr), 4-stage cp.async ----
__global__ __launch_bounds__(128)
void bgemm(const ushortt* __restrict__ A0, const ushortt* __restrict__ A1, int lda,
           const ushortt* __restrict__ W0, const ushortt* __restrict__ W1, int ldw,
           const float* bx0, const float* by0, const float* bx1, const float* by1,
           float* C0, float* C1, int ldc, int K)
{
    __shared__ __align__(16) ushortt sm[4][4][1536];   // 4 stages x 12288B = 48KB
    const int z = blockIdx.z;
    const ushortt* A = z ? A1 : A0;
    const ushortt* W = z ? W1 : W0;
    const float* bx = z ? bx1 : bx0;
    const float* by = z ? by1 : by0;
    float* C = z ? C1 : C0;
    const int m0 = blockIdx.y * 64, n0 = blockIdx.x * 64;
    const int Mt = gridDim.y * 64, Nt = gridDim.x * 64;
    const ushortt* Ah = A + (size_t)m0 * lda;
    const ushortt* Al = Ah + (size_t)Mt * lda;
    const ushortt* Wh = W + (size_t)n0 * ldw;
    const ushortt* Wl = Wh + (size_t)Nt * ldw;
    const int tid = threadIdx.x, w = tid >> 5, L = tid & 31;
    const int wm = (w & 1) * 32, wn = (w >> 1) * 32;
    const uint32_t sb = smem_u32(sm);
    const int r = (L & 7) + ((L >> 3) & 1) * 8, ko = ((L >> 4) & 1) * 16;
    const uint32_t oA0 = (uint32_t)((wm + r) * 48 + ko), oA1 = (uint32_t)((wm + 16 + r) * 48 + ko);
    const int br = (L & 7) + ((L >> 4) & 1) * 8, bko = ((L >> 3) & 1) * 16;
    const uint32_t oB0 = (uint32_t)((wn + br) * 48 + bko), oB1 = (uint32_t)((wn + 16 + br) * 48 + bko);
    const int row = tid >> 1, hf = tid & 1;

    float c[2][4][4];
#pragma unroll
    for (int i = 0; i < 2; i++)
#pragma unroll
        for (int j = 0; j < 4; j++)
#pragma unroll
            for (int q = 0; q < 4; q++) c[i][j][q] = 0.f;

    const int T = K >> 4;
    const uint32_t dbase = sb + (uint32_t)(row * 48 + hf * 16);
    const size_t goffA = (size_t)row * lda + hf * 8;
    const size_t goffW = (size_t)row * ldw + hf * 8;

#define ISSUE(stg, k0) do { \
    uint32_t bp = dbase + (uint32_t)(stg) * 12288u; \
    CPA(bp,        (const void*)(Ah + goffA + (k0))); \
    CPA(bp + 3072, (const void*)(Al + goffA + (k0))); \
    CPA(bp + 6144, (const void*)(Wh + goffW + (k0))); \
    CPA(bp + 9216, (const void*)(Wl + goffW + (k0))); } while (0)

    ISSUE(0, 0);
    CPA_COMMIT();
    ISSUE(1, 16);
    CPA_COMMIT();
    if (T > 2) ISSUE(2, 32);
    CPA_COMMIT();

    for (int t = 0; t < T; t++) {
        if (t + 3 < T) ISSUE((t + 3) & 3, (t + 3) << 4);
        CPA_COMMIT();
        CPA_WAIT3();
        __syncthreads();
        {
            uint32_t base = sb + (uint32_t)((t & 3) * 12288);
            uint32_t ah[2][4], alr[2][4], bh[2][4], bl[2][4];
            LDSM4(ah[0], base + oA0);
            LDSM4(ah[1], base + oA1);
            LDSM4(alr[0], base + 3072 + oA0);
            LDSM4(alr[1], base + 3072 + oA1);
            LDSM4(bh[0], base + 6144 + oB0);
            LDSM4(bh[1], base + 6144 + oB1);
            LDSM4(bl[0], base + 9216 + oB0);
            LDSM4(bl[1], base + 9216 + oB1);
#pragma unroll
            for (int mf = 0; mf < 2; mf++)
#pragma unroll
                for (int nf = 0; nf < 4; nf++) {
                    int g = nf >> 1, o = (nf & 1) * 2;
                    MMA(c[mf][nf], ah[mf], bh[g][o], bh[g][o + 1]);
                    MMA(c[mf][nf], ah[mf], bl[g][o], bl[g][o + 1]);
                    MMA(c[mf][nf], alr[mf], bh[g][o], bh[g][o + 1]);
                }
        }
        __syncthreads();
    }
    const int g2 = L >> 2, qc = (L & 3) * 2;
#pragma unroll
    for (int nf = 0; nf < 4; nf++) {
        int col = n0 + wn + nf * 8 + qc;
        float b0 = 0.f, b1 = 0.f;
        if (bx) { b0 += bx[col]; b1 += bx[col + 1]; }
        if (by) { b0 += by[col]; b1 += by[col + 1]; }
#pragma unroll
        for (int mf = 0; mf < 2; mf++) {
            int rw = m0 + wm + mf * 16 + g2;
            *(float2*)(C + (size_t)rw * ldc + col) = make_float2(c[mf][nf][0] + b0, c[mf][nf][1] + b1);
            *(float2*)(C + (size_t)(rw + 8) * ldc + col) = make_float2(c[mf][nf][2] + b0, c[mf][nf][3] + b1);
        }
    }
}

// ---- fused weight prep + embedding ----
#define PN0 (BL * 400)
#define PN1 (1024 * 400)
#define PN3 (512 * 512)
#define PN5 (1024 * KC1P)
#define PN6 (1024 * KFP)
#define N_PREP (PN0 + 2 * PN1 + 2 * PN3 + PN5 + PN6)
__global__ void prep_w(const int* __restrict__ toks, const float* __restrict__ mask,
                       const float* __restrict__ gen, const float* __restrict__ dom,
                       const float* __restrict__ wf, const float* __restrict__ wb,
                       const float* __restrict__ wq, const float* __restrict__ wk,
                       const float* __restrict__ fw, ushortt* EB,
                       ushortt* WIHF, ushortt* WIHB, ushortt* WQB, ushortt* WKB,
                       ushortt* WUC, ushortt* WVC, ushortt* WP) {
    int idx = blockIdx.x * blockDim.x + threadIdx.x;
    ushortt h, l;
    if (idx < PN0) {
        int rowi = idx / 400, j = idx % 400;
        int tok = toks[rowi];
        float v = ((j < 300) ? gen[tok * 300 + j] : dom[tok * 100 + (j - 300)]) * mask[rowi];
        bsplit(v, h, l);
        EB[idx] = h; EB[PN0 + idx] = l;
        return;
    }
    idx -= PN0;
    if (idx < PN1) { bsplit(wf[idx], h, l); WIHF[idx] = h; WIHF[PN1 + idx] = l; return; }
    idx -= PN1;
    if (idx < PN1) { bsplit(wb[idx], h, l); WIHB[idx] = h; WIHB[PN1 + idx] = l; return; }
    idx -= PN1;
    if (idx < PN3) { bsplit(wq[idx], h, l); WQB[idx] = h; WQB[PN3 + idx] = l; return; }
    idx -= PN3;
    if (idx < PN3) { bsplit(wk[idx], h, l); WKB[idx] = h; WKB[PN3 + idx] = l; return; }
    idx -= PN3;
    if (idx < PN5) {
        int nn = idx / KC1P, j = idx % KC1P;
        float u = 0.f, v = 0.f;
        if (j < 524) {
            int sU = (j < 512) ? j : ((j < 518) ? 1024 + (j - 512) : 1036 + (j - 518));
            int sV = (j < 512) ? 512 + j : ((j < 518) ? 1030 + (j - 512) : 1036 + (j - 518));
            u = fw[(size_t)nn * KFULL + sU];
            v = fw[(size_t)nn * KFULL + sV];
        }
        bsplit(u, h, l); WUC[idx] = h; WUC[PN5 + idx] = l;
        bsplit(v, h, l); WVC[idx] = h; WVC[PN5 + idx] = l;
        return;
    }
    idx -= PN5;
    if (idx < PN6) {
        int nn = idx / KFP, j = idx % KFP;
        float v = (j < KFULL) ? fw[(size_t)nn * KFULL + j] : 0.f;
        bsplit(v, h, l);
        WP[idx] = h;
        WP[PN6 + idx] = l;
    }
}

// ---- BiLSTM: 8-CTA clusters, barrier.cluster per step ----
__global__ __launch_bounds__(256, 1) __cluster_dims__(8, 1, 1)
void lstm_cluster(const float* __restrict__ whh_f, const float* __restrict__ whh_b,
                  const float* __restrict__ pre, float* __restrict__ ctx,
                  ushortt* __restrict__ ctxb) {
    __shared__ float hb[2][264];
    const int tid = threadIdx.x;
    unsigned rank;
    asm("mov.u32 %0, %%cluster_ctarank;" : "=r"(rank));
    const int cid = blockIdx.x >> 3, dir = cid >> 2, batch = cid & 3;
    const int ct = (int)rank * 256 + tid;
    const int half = ct & 1, p = ct >> 1, gate = p & 3, d = p >> 2;
    const int gbase = (tid & 31) & ~7;
    const int lane7 = tid & 7;
    const bool prod = (tid & 7) == 0;
    const int dslot = (d < 128) ? d : d + 4;
    const float* whh = dir ? whh_b : whh_f;
    ulonglong2 w2[32];
    const ulonglong2* wp = (const ulonglong2*)(whh + ((size_t)(gate * 256 + d)) * 256 + half * 128);
#pragma unroll
    for (int i = 0; i < 32; i++) w2[i] = wp[i];
    for (int j = tid; j < 264; j += 256) hb[0][j] = 0.f;
    const float* preB = pre + ((size_t)dir * 512 + batch * 128) * 1024 + gate * 256 + d;
    float* ctxB = ctx + ((size_t)batch * 128) * 512 + dir * 256 + d;
    ushortt* cbB = ctxb + ((size_t)batch * 128) * 512 + dir * 256 + d;
    uint32_t la0 = smem_u32(&hb[0][dslot]);
    uint32_t la1 = smem_u32(&hb[1][dslot]);
    asm volatile("barrier.cluster.arrive.aligned;" ::: "memory");
    float preCur = preB[(size_t)(dir ? 127 : 0) * 1024];
    float cc = 0.f;
    for (int s = 0; s < 128; s++) {
        asm volatile("barrier.cluster.wait.aligned;" ::: "memory");
        const ulonglong2* hp = (const ulonglong2*)(&hb[s & 1][half ? 132 : 0]);
        unsigned long long a0 = 0ull, a1 = 0ull, a2 = 0ull, a3 = 0ull;
#pragma unroll
        for (int i = 0; i < 32; i += 2) {
            ulonglong2 h0 = hp[i], h1 = hp[i + 1];
            FMA2(a0, w2[i].x, h0.x);
            FMA2(a1, w2[i].y, h0.y);
            FMA2(a2, w2[i + 1].x, h1.x);
            FMA2(a3, w2[i + 1].y, h1.y);
        }
        float x0, x1, y0, y1, z0, z1, u0, u1;
        asm("mov.b64 {%0, %1}, %2;" : "=f"(x0), "=f"(x1) : "l"(a0));
        asm("mov.b64 {%0, %1}, %2;" : "=f"(y0), "=f"(y1) : "l"(a1));
        asm("mov.b64 {%0, %1}, %2;" : "=f"(z0), "=f"(z1) : "l"(a2));
        asm("mov.b64 {%0, %1}, %2;" : "=f"(u0), "=f"(u1) : "l"(a3));
        float acc = ((x0 + x1) + (y0 + y1)) + ((z0 + z1) + (u0 + u1));
        acc += __shfl_xor_sync(0xffffffffu, acc, 1);
        float gv = acc + preCur;
        float act = (gate == 2) ? ftanh(gv) : fsig(gv);
        float aI = __shfl_sync(0xffffffffu, act, gbase);
        float aF = __shfl_sync(0xffffffffu, act, gbase + 2);
        float aG = __shfl_sync(0xffffffffu, act, gbase + 4);
        float aO = __shfl_sync(0xffffffffu, act, gbase + 6);
        float hv = 0.f;
        if (prod) {
            cc = aF * cc + aI * aG;
            hv = aO * ftanh(cc);
        }
        hv = __shfl_sync(0xffffffffu, hv, gbase);
        if (s < 127) {
            uint32_t la = ((s + 1) & 1) ? la1 : la0;
            uint32_t ra;
            asm("mapa.shared::cluster.u32 %0, %1, %2;" : "=r"(ra) : "r"(la), "r"(lane7));
            asm volatile("st.shared::cluster.f32 [%0], %1;" :: "r"(ra), "f"(hv));
        }
        asm volatile("barrier.cluster.arrive.aligned;" ::: "memory");
        int time = dir ? (127 - s) : s;
        if (prod) {
            ctxB[(size_t)time * 512] = hv;
            ushortt hh, ll;
            bsplit(hv, hh, ll);
            cbB[(size_t)time * 512] = hh;
            cbB[(size_t)(512 * 512) + (size_t)time * 512] = ll;
        }
        if (s < 127) preCur = preB[(size_t)(dir ? (126 - s) : (s + 1)) * 1024];
    }
    asm volatile("barrier.cluster.wait.aligned;" ::: "memory");
}

// ---- attention + residual, fused with hop-0 F/G classifier dots ----
__global__ __launch_bounds__(256)
void attn_kernel(const float* __restrict__ q, const float* __restrict__ k,
                 const float* __restrict__ ctx, float* __restrict__ ctx2,
                 const float* __restrict__ cls_w, const float* __restrict__ cls_b,
                 float* __restrict__ F, float* __restrict__ G) {
    int row = blockIdx.x, b = row >> 7, tid = threadIdx.x;
    __shared__ float qsh[512], sc[128], red[128];
    for (int j = tid; j < 512; j += 256) qsh[j] = q[(size_t)row * 512 + j];
    __syncthreads();
    {
        int m = tid >> 1, half = tid & 1;
        const float* kr = k + ((size_t)(b * 128 + m)) * 512 + half * 256;
        const float* qh = qsh + half * 256;
        float s = 0.f;
#pragma unroll 8
        for (int j = 0; j < 256; j++) s = fmaf(qh[j], kr[j], s);
        s += __shfl_xor_sync(0xffffffffu, s, 1);
        if (!half) sc[m] = s;
    }
    __syncthreads();
    if (tid < 128) red[tid] = sc[tid];
    __syncthreads();
    for (int s = 64; s > 0; s >>= 1) {
        if (tid < s) red[tid] = fmaxf(red[tid], red[tid + s]);
        __syncthreads();
    }
    float mx = red[0];
    __syncthreads();
    if (tid < 128) { float e = __expf(sc[tid] - mx); sc[tid] = e; red[tid] = e; }
    __syncthreads();
    for (int s = 64; s > 0; s >>= 1) {
        if (tid < s) red[tid] += red[tid + s];
        __syncthreads();
    }
    float inv = 1.f / red[0];
    __syncthreads();
    int c0 = tid * 2;
    float o0 = 0.f, o1 = 0.f;
    for (int m = 0; m < 128; m++) {
        float a = sc[m] * inv;
        float2 cv = *(const float2*)(ctx + ((size_t)(b * 128 + m)) * 512 + c0);
        o0 = fmaf(a, cv.x, o0);
        o1 = fmaf(a, cv.y, o1);
    }
    float2 bs = *(const float2*)(ctx + (size_t)row * 512 + c0);
    float r0 = o0 + bs.x, r1 = o1 + bs.y;
    *(float2*)(ctx2 + (size_t)row * 512 + c0) = make_float2(r0, r1);
    // stash ctx2 row in smem and compute F/G = row . cls_w halves
    __syncthreads();
    qsh[c0] = r0;
    qsh[c0 + 1] = r1;
    __syncthreads();
    int w = tid >> 5, L2 = tid & 31;
    for (int c = w; c < 12; c += 8) {
        const float* wv = cls_w + (size_t)(c % 6) * 1024 + (c >= 6 ? 512 : 0);
        float a = 0.f;
        for (int i = L2; i < 128; i += 32) {
            float4 x = *(const float4*)(qsh + i * 4);
            float4 ww = *(const float4*)(wv + i * 4);
            a += x.x * ww.x + x.y * ww.y + x.z * ww.z + x.w * ww.w;
        }
#pragma unroll
        for (int sft = 16; sft > 0; sft >>= 1) a += __shfl_xor_sync(0xffffffffu, a, sft);
        if (L2 == 0) {
            if (c < 6) F[(size_t)row * Cn + c] = a + cls_b[c];
            else G[(size_t)row * Cn + (c - 6)] = a;
        }
    }
}

__global__ __launch_bounds__(256)
void smallmm3(const float* __restrict__ A0, const float* __restrict__ A1, int lda, int K,
              const float* __restrict__ W, int ldw, int off0, int off1,
              const float* __restrict__ bias, float* __restrict__ C0, float* __restrict__ C1) {
    int z = blockIdx.z;
    int w = threadIdx.x >> 5, L = threadIdx.x & 31;
    int row = blockIdx.x * 8 + w;
    const float* A = (z ? A1 : A0) + (size_t)row * lda;
    int off = z ? off1 : off0;
    float acc[Cn] = {0, 0, 0, 0, 0, 0};
    for (int i = L; i * 4 < K; i += 32) {
        float4 a = *(const float4*)(A + i * 4);
#pragma unroll
        for (int c = 0; c < Cn; c++) {
            float4 wv = *(const float4*)(W + (size_t)c * ldw + off + i * 4);
            acc[c] += a.x * wv.x + a.y * wv.y + a.z * wv.z + a.w * wv.w;
        }
    }
#pragma unroll
    for (int sft = 16; sft > 0; sft >>= 1)
#pragma unroll
        for (int c = 0; c < Cn; c++) acc[c] += __shfl_xor_sync(0xffffffffu, acc[c], sft);
    if (L == 0) {
        float* C = (z ? C1 : C0) + (size_t)row * Cn;
#pragma unroll
        for (int c = 0; c < Cn; c++) C[c] = acc[c] + ((z == 0 && bias) ? bias[c] : 0.f);
    }
}

static __device__ __forceinline__ void row_lm(const float* F, const float* G,
                                              int b, int l, float* lmsh) {
    int tid = threadIdx.x;
    if (tid < 192) {
        int c = tid >> 5, lane = tid & 31;
        const float* Fb = F + (size_t)(b * Ln) * Cn + c;
        const float* Gb = G + (size_t)(b * Ln) * Cn + c;
        float pf = -3.0e38f, sg = -3.0e38f;
        for (int l2 = lane; l2 <= l; l2 += 32) pf = fmaxf(pf, Fb[l2 * Cn]);
        for (int l2 = l + lane; l2 < Ln; l2 += 32) sg = fmaxf(sg, Gb[l2 * Cn]);
#pragma unroll
        for (int sft = 16; sft > 0; sft >>= 1) {
            pf = fmaxf(pf, __shfl_xor_sync(0xffffffffu, pf, sft));
            sg = fmaxf(sg, __shfl_xor_sync(0xffffffffu, sg, sft));
        }
        if (lane == 0) {
            float v1 = Gb[l * Cn] + pf;
            if (l < Ln - 1) v1 = fmaxf(v1, 0.f);
            float v2 = Fb[l * Cn] + sg;
            if (l > 0) v2 = fmaxf(v2, 0.f);
            lmsh[c] = fmaxf(v1, v2);
        }
    }
    __syncthreads();
}

__global__ __launch_bounds__(256)
void build_ab1(const float* __restrict__ ctx2, const float* __restrict__ F,
               const float* __restrict__ G,
               ushortt* __restrict__ AbU, ushortt* __restrict__ AbV) {
    int row = blockIdx.x;
    __shared__ float lmsh[8];
    row_lm(F, G, row >> 7, row & 127, lmsh);
    const int n = BL * KC1P;
    for (int j = threadIdx.x; j < KC1P; j += blockDim.x) {
        float u = 0.f, v = 0.f;
        if (j < 512) { u = v = ctx2[(size_t)row * 512 + j]; }
        else if (j < 518) { u = v = lmsh[j - 512]; }
        else if (j < 524) { u = F[(size_t)row * Cn + (j - 518)]; v = G[(size_t)row * Cn + (j - 518)]; }
        ushortt h, l;
        int idx = row * KC1P + j;
        bsplit(u, h, l); AbU[idx] = h; AbU[n + idx] = l;
        bsplit(v, h, l); AbV[idx] = h; AbV[n + idx] = l;
    }
}

__global__ __launch_bounds__(256)
void build_bar(const float* __restrict__ U, const float* __restrict__ V,
               const float* __restrict__ F, const float* __restrict__ G,
               ushortt* __restrict__ Ub, ushortt* __restrict__ Vb) {
    int row = blockIdx.x;
    __shared__ float lmsh[8];
    row_lm(F, G, row >> 7, row & 127, lmsh);
    const int n = BL * KFP;
    for (int j = threadIdx.x; j < KFP; j += blockDim.x) {
        float u = 0.f, v = 0.f;
        if (j < 1024) { u = U[(size_t)row * 1024 + j]; v = V[(size_t)row * 1024 + j]; }
        else if (j < 1030) { u = lmsh[j - 1024]; }
        else if (j < 1036) { v = lmsh[j - 1030]; }
        else if (j < 1042) { u = F[(size_t)row * Cn + (j - 1036)]; v = G[(size_t)row * Cn + (j - 1036)]; }
        ushortt h, l;
        int idx = row * KFP + j;
        bsplit(u, h, l); Ub[idx] = h; Ub[n + idx] = l;
        bsplit(v, h, l); Vb[idx] = h; Vb[n + idx] = l;
    }
}

__global__ void final_kernel(const float* __restrict__ F, const float* __restrict__ G, float* __restrict__ out) {
    int idx = blockIdx.x * blockDim.x + threadIdx.x;
    if (idx >= Bn * Ln * Ln * Cn) return;
    int c = idx % Cn, j = (idx / Cn) % Ln, i = (idx / (Cn * Ln)) % Ln, b = idx / (Cn * Ln * Ln);
    out[idx] = F[((size_t)(b * Ln + i)) * Cn + c] + G[((size_t)(b * Ln + j)) * Cn + c];
}

extern "C" void kernel_launch(void* const* d_in, const int* in_sizes, int n_in,
                              void* d_out, int out_size) {
    (void)in_sizes; (void)n_in; (void)out_size;
    const int* toks = (const int*)d_in[0];
    const float* mask = (const float*)d_in[2];
    const float* gen = (const float*)d_in[3];
    const float* dom = (const float*)d_in[4];
    const float* wih_f = (const float*)d_in[5];
    const float* whh_f = (const float*)d_in[6];
    const float* bih_f = (const float*)d_in[7];
    const float* bhh_f = (const float*)d_in[8];
    const float* wih_b = (const float*)d_in[9];
    const float* whh_b = (const float*)d_in[10];
    const float* bih_b = (const float*)d_in[11];
    const float* bhh_b = (const float*)d_in[12];
    const float* wq = (const float*)d_in[13];
    const float* bq = (const float*)d_in[14];
    const float* wk = (const float*)d_in[15];
    const float* bk = (const float*)d_in[16];
    const float* feat_w = (const float*)d_in[17];
    const float* feat_b = (const float*)d_in[18];
    const float* cls_w = (const float*)d_in[19];
    const float* cls_b = (const float*)d_in[20];
    float* out = (float*)d_out;

    float* S = nullptr;
    cudaGetSymbolAddress((void**)&S, d_scratch);
    ushortt* EB   = (ushortt*)(S + O_EB);
    ushortt* WIHF = (ushortt*)(S + O_WIHF);
    ushortt* WIHB = (ushortt*)(S + O_WIHB);
    float* pre  = S + O_PRE;
    float* ctx  = S + O_CTX;
    ushortt* CTXB = (ushortt*)(S + O_CTXB);
    ushortt* WQB  = (ushortt*)(S + O_WQB);
    ushortt* WKB  = (ushortt*)(S + O_WKB);
    float* qb = S + O_Q;
    float* kb = S + O_K;
    float* ctx2 = S + O_CTX2;
    float* F = S + O_F;   float* G = S + O_G;
    float* F2 = S + O_F2; float* G2 = S + O_G2;
    float* U = S + O_U;   float* V = S + O_V;
    float* U2 = S + O_U2; float* V2 = S + O_V2;
    ushortt* ABUB = (ushortt*)(S + O_ABUB);
    ushortt* ABVB = (ushortt*)(S + O_ABVB);
    ushortt* WUCB = (ushortt*)(S + O_WUCB);
    ushortt* WVCB = (ushortt*)(S + O_WVCB);
    ushortt* WPB  = (ushortt*)(S + O_WPB);
    ushortt* UBB  = (ushortt*)(S + O_UBB);
    ushortt* VBB  = (ushortt*)(S + O_VBB);

    prep_w<<<(N_PREP + 255) / 256, 256>>>(toks, mask, gen, dom, wih_f, wih_b, wq, wk, feat_w,
                                          EB, WIHF, WIHB, WQB, WKB, WUCB, WVCB, WPB);
    bgemm<<<dim3(16, 8, 2), 128>>>(EB, EB, 400, WIHF, WIHB, 400,
                                   bih_f, bhh_f, bih_b, bhh_b,
                                   pre, pre + (size_t)BL * 1024, 1024, 400);
    lstm_cluster<<<64, 256>>>(whh_f, whh_b, pre, ctx, CTXB);
    bgemm<<<dim3(8, 8, 2), 128>>>(CTXB, CTXB, 512, WQB, WKB, 512,
                                  bq, nullptr, bk, nullptr, qb, kb, 512, 512);
    attn_kernel<<<BL, 256>>>(qb, kb, ctx, ctx2, cls_w, cls_b, F, G);
    build_ab1<<<BL, 256>>>(ctx2, F, G, ABUB, ABVB);
    bgemm<<<dim3(16, 8, 2), 128>>>(ABUB, ABVB, KC1P, WUCB, WVCB, KC1P,
                                   feat_b, nullptr, nullptr, nullptr, U, V, 1024, KC1P);
    smallmm3<<<dim3(BL / 8, 1, 2), 256>>>(U, V, 1024, 1024, cls_w, 1024, 0, 0, cls_b, F2, G2);
    build_bar<<<BL, 256>>>(U, V, F2, G2, UBB, VBB);
    bgemm<<<dim3(16, 8, 2), 128>>>(UBB, VBB, KFP, WPB, WPB, KFP,
                                   feat_b, nullptr, nullptr, nullptr, U2, V2, 1024, KFP);
    smallmm3<<<dim3(BL / 8, 1, 2), 256>>>(U2, V2, 1024, 1024, cls_w, 1024, 0, 0, cls_b, F, G);
    final_kernel<<<1536, 256>>>(F, G, out);
}

// round 16
// speedup vs baseline: 1.5869x; 1.0190x over previous
#include <cuda_runtime.h>
#include <cuda_bf16.h>
#include <math.h>
#include <stdint.h>

typedef unsigned short ushortt;

#define Bn 4
#define Ln 128
#define Cn 6
#define BL 512
#define KC1P 528
#define KFP 1056
#define KFULL 1042

#define O_EB    0
#define O_WIHF  (O_EB + 204800)
#define O_WIHB  (O_WIHF + 409600)
#define O_PRE   (O_WIHB + 409600)
#define O_CTX   (O_PRE + 1048576)
#define O_CTXB  (O_CTX + 262144)
#define O_WQB   (O_CTXB + 262144)
#define O_WKB   (O_WQB + 262144)
#define O_Q     (O_WKB + 262144)
#define O_K     (O_Q + 262144)
#define O_CTX2  (O_K + 262144)
#define O_F     (O_CTX2 + 262144)
#define O_G     (O_F + 3072)
#define O_F2    (O_G + 3072)
#define O_G2    (O_F2 + 3072)
#define O_U     (O_G2 + 3072)
#define O_V     (O_U + 524288)
#define O_U2    (O_V + 524288)
#define O_V2    (O_U2 + 524288)
#define O_ABUB  (O_V2 + 524288)
#define O_ABVB  (O_ABUB + 270336)
#define O_WUCB  (O_ABVB + 270336)
#define O_WVCB  (O_WUCB + 540672)
#define O_WPB   (O_WVCB + 540672)
#define O_UBB   (O_WPB + 1081344)
#define O_VBB   (O_UBB + 540672)
#define SCRATCH_TOTAL (O_VBB + 540672)
__device__ __align__(256) float d_scratch[SCRATCH_TOTAL];

static __device__ __forceinline__ uint32_t smem_u32(const void* p) {
    uint32_t a;
    asm("{ .reg .u64 t; cvta.to.shared.u64 t, %1; cvt.u32.u64 %0, t; }" : "=r"(a) : "l"(p));
    return a;
}
static __device__ __forceinline__ void bsplit(float v, ushortt& h, ushortt& l) {
    __nv_bfloat16 hb = __float2bfloat16_rn(v);
    __nv_bfloat16 lb = __float2bfloat16_rn(v - __bfloat162float(hb));
    h = __bfloat16_as_ushort(hb);
    l = __bfloat16_as_ushort(lb);
}
static __device__ __forceinline__ float fsig(float x) {
    return __fdividef(1.f, 1.f + __expf(-x));
}
static __device__ __forceinline__ float ftanh(float x) {
    return 1.f - __fdividef(2.f, __expf(2.f * x) + 1.f);
}
#define LDSM4(R, a) asm volatile("ldmatrix.sync.aligned.m8n8.x4.shared.b16 {%0,%1,%2,%3}, [%4];" \
    : "=r"((R)[0]), "=r"((R)[1]), "=r"((R)[2]), "=r"((R)[3]) : "r"(a))
#define MMA(c, a, b0, b1) asm volatile( \
    "mma.sync.aligned.m16n8k16.row.col.f32.bf16.bf16.f32 {%0,%1,%2,%3},{%4,%5,%6,%7},{%8,%9},{%0,%1,%2,%3};" \
    : "+f"((c)[0]), "+f"((c)[1]), "+f"((c)[2]), "+f"((c)[3]) \
    : "r"((a)[0]), "r"((a)[1]), "r"((a)[2]), "r"((a)[3]), "r"(b0), "r"(b1))
#define FMA2(acc, a, b) asm("fma.rn.f32x2 %0, %1, %2, %0;" : "+l"(acc) : "l"(a), "l"(b))
#define CPA(dst, src) asm volatile("cp.async.cg.shared.global [%0], [%1], 16;" \
    :: "r"(dst), "l"(src) : "memory")
#define CPA_COMMIT() asm volatile("cp.async.commit_group;" ::: "memory")
#define CPA_WAIT3() asm volatile("cp.async.wait_group 3;" ::: "memory")

// ---- bf16 hi/lo tensor-core GEMM (64x64 tiles, 128 thr), 4-stage cp.async ----
__global__ __launch_bounds__(128)
void bgemm(const ushortt* __restrict__ A0, const ushortt* __restrict__ A1, int lda,
           const ushortt* __restrict__ W0, const ushortt* __restrict__ W1, int ldw,
           const float* bx0, const float* by0, const float* bx1, const float* by1,
           float* C0, float* C1, int ldc, int K)
{
    __shared__ __align__(16) ushortt sm[4][4][1536];
    const int z = blockIdx.z;
    const ushortt* A = z ? A1 : A0;
    const ushortt* W = z ? W1 : W0;
    const float* bx = z ? bx1 : bx0;
    const float* by = z ? by1 : by0;
    float* C = z ? C1 : C0;
    const int m0 = blockIdx.y * 64, n0 = blockIdx.x * 64;
    const int Mt = gridDim.y * 64, Nt = gridDim.x * 64;
    const ushortt* Ah = A + (size_t)m0 * lda;
    const ushortt* Al = Ah + (size_t)Mt * lda;
    const ushortt* Wh = W + (size_t)n0 * ldw;
    const ushortt* Wl = Wh + (size_t)Nt * ldw;
    const int tid = threadIdx.x, w = tid >> 5, L = tid & 31;
    const int wm = (w & 1) * 32, wn = (w >> 1) * 32;
    const uint32_t sb = smem_u32(sm);
    const int r = (L & 7) + ((L >> 3) & 1) * 8, ko = ((L >> 4) & 1) * 16;
    const uint32_t oA0 = (uint32_t)((wm + r) * 48 + ko), oA1 = (uint32_t)((wm + 16 + r) * 48 + ko);
    const int br = (L & 7) + ((L >> 4) & 1) * 8, bko = ((L >> 3) & 1) * 16;
    const uint32_t oB0 = (uint32_t)((wn + br) * 48 + bko), oB1 = (uint32_t)((wn + 16 + br) * 48 + bko);
    const int row = tid >> 1, hf = tid & 1;

    float c[2][4][4];
#pragma unroll
    for (int i = 0; i < 2; i++)
#pragma unroll
        for (int j = 0; j < 4; j++)
#pragma unroll
            for (int q = 0; q < 4; q++) c[i][j][q] = 0.f;

    const int T = K >> 4;
    const uint32_t dbase = sb + (uint32_t)(row * 48 + hf * 16);
    const size_t goffA = (size_t)row * lda + hf * 8;
    const size_t goffW = (size_t)row * ldw + hf * 8;

#define ISSUE(stg, k0) do { \
    uint32_t bp = dbase + (uint32_t)(stg) * 12288u; \
    CPA(bp,        (const void*)(Ah + goffA + (k0))); \
    CPA(bp + 3072, (const void*)(Al + goffA + (k0))); \
    CPA(bp + 6144, (const void*)(Wh + goffW + (k0))); \
    CPA(bp + 9216, (const void*)(Wl + goffW + (k0))); } while (0)

    ISSUE(0, 0);
    CPA_COMMIT();
    ISSUE(1, 16);
    CPA_COMMIT();
    if (T > 2) ISSUE(2, 32);
    CPA_COMMIT();

    for (int t = 0; t < T; t++) {
        if (t + 3 < T) ISSUE((t + 3) & 3, (t + 3) << 4);
        CPA_COMMIT();
        CPA_WAIT3();
        __syncthreads();
        {
            uint32_t base = sb + (uint32_t)((t & 3) * 12288);
            uint32_t ah[2][4], alr[2][4], bh[2][4], bl[2][4];
            LDSM4(ah[0], base + oA0);
            LDSM4(ah[1], base + oA1);
            LDSM4(alr[0], base + 3072 + oA0);
            LDSM4(alr[1], base + 3072 + oA1);
            LDSM4(bh[0], base + 6144 + oB0);
            LDSM4(bh[1], base + 6144 + oB1);
            LDSM4(bl[0], base + 9216 + oB0);
            LDSM4(bl[1], base + 9216 + oB1);
#pragma unroll
            for (int mf = 0; mf < 2; mf++)
#pragma unroll
                for (int nf = 0; nf < 4; nf++) {
                    int g = nf >> 1, o = (nf & 1) * 2;
                    MMA(c[mf][nf], ah[mf], bh[g][o], bh[g][o + 1]);
                    MMA(c[mf][nf], ah[mf], bl[g][o], bl[g][o + 1]);
                    MMA(c[mf][nf], alr[mf], bh[g][o], bh[g][o + 1]);
                }
        }
        __syncthreads();
    }
    const int g2 = L >> 2, qc = (L & 3) * 2;
#pragma unroll
    for (int nf = 0; nf < 4; nf++) {
        int col = n0 + wn + nf * 8 + qc;
        float b0 = 0.f, b1 = 0.f;
        if (bx) { b0 += bx[col]; b1 += bx[col + 1]; }
        if (by) { b0 += by[col]; b1 += by[col + 1]; }
#pragma unroll
        for (int mf = 0; mf < 2; mf++) {
            int rw = m0 + wm + mf * 16 + g2;
            *(float2*)(C + (size_t)rw * ldc + col) = make_float2(c[mf][nf][0] + b0, c[mf][nf][1] + b1);
            *(float2*)(C + (size_t)(rw + 8) * ldc + col) = make_float2(c[mf][nf][2] + b0, c[mf][nf][3] + b1);
        }
    }
}

// ---- weight prep part 1 (needed before bgemm1): embedding + wih/wq/wk ----
#define PN0 (BL * 400)
#define PN1 (1024 * 400)
#define PN3 (512 * 512)
#define PN5 (1024 * KC1P)
#define PN6 (1024 * KFP)
#define N_PREP (PN0 + 2 * PN1 + 2 * PN3)
__global__ void prep_w(const int* __restrict__ toks, const float* __restrict__ mask,
                       const float* __restrict__ gen, const float* __restrict__ dom,
                       const float* __restrict__ wf, const float* __restrict__ wb,
                       const float* __restrict__ wq, const float* __restrict__ wk,
                       ushortt* EB, ushortt* WIHF, ushortt* WIHB, ushortt* WQB, ushortt* WKB) {
    int idx = blockIdx.x * blockDim.x + threadIdx.x;
    ushortt h, l;
    if (idx < PN0) {
        int rowi = idx / 400, j = idx % 400;
        int tok = toks[rowi];
        float v = ((j < 300) ? gen[tok * 300 + j] : dom[tok * 100 + (j - 300)]) * mask[rowi];
        bsplit(v, h, l);
        EB[idx] = h; EB[PN0 + idx] = l;
        return;
    }
    idx -= PN0;
    if (idx < PN1) { bsplit(wf[idx], h, l); WIHF[idx] = h; WIHF[PN1 + idx] = l; return; }
    idx -= PN1;
    if (idx < PN1) { bsplit(wb[idx], h, l); WIHB[idx] = h; WIHB[PN1 + idx] = l; return; }
    idx -= PN1;
    if (idx < PN3) { bsplit(wq[idx], h, l); WQB[idx] = h; WQB[PN3 + idx] = l; return; }
    idx -= PN3;
    if (idx < PN3) { bsplit(wk[idx], h, l); WKB[idx] = h; WKB[PN3 + idx] = l; return; }
}

// ---- BiLSTM (clusters 0-7) + co-scheduled feat_w prep (clusters 8-15) ----
__global__ __launch_bounds__(256, 1) __cluster_dims__(8, 1, 1)
void lstm_cluster(const float* __restrict__ whh_f, const float* __restrict__ whh_b,
                  const float* __restrict__ pre, float* __restrict__ ctx,
                  ushortt* __restrict__ ctxb,
                  const float* __restrict__ fw, ushortt* __restrict__ WUC,
                  ushortt* __restrict__ WVC, ushortt* __restrict__ WP) {
    __shared__ float hb[2][264];
    const int tid = threadIdx.x;
    const int cid = blockIdx.x >> 3;
    if (cid >= 8) {
        const int NT = 64 * 256;
        int tidg = (blockIdx.x - 64) * 256 + tid;
        ushortt h, l;
        for (int idx = tidg; idx < PN5; idx += NT) {
            int nn = idx / KC1P, j = idx % KC1P;
            float u = 0.f, v = 0.f;
            if (j < 524) {
                int sU = (j < 512) ? j : ((j < 518) ? 1024 + (j - 512) : 1036 + (j - 518));
                int sV = (j < 512) ? 512 + j : ((j < 518) ? 1030 + (j - 512) : 1036 + (j - 518));
                u = fw[(size_t)nn * KFULL + sU];
                v = fw[(size_t)nn * KFULL + sV];
            }
            bsplit(u, h, l); WUC[idx] = h; WUC[PN5 + idx] = l;
            bsplit(v, h, l); WVC[idx] = h; WVC[PN5 + idx] = l;
        }
        for (int idx = tidg; idx < PN6; idx += NT) {
            int nn = idx / KFP, j = idx % KFP;
            float v = (j < KFULL) ? fw[(size_t)nn * KFULL + j] : 0.f;
            bsplit(v, h, l);
            WP[idx] = h;
            WP[PN6 + idx] = l;
        }
        return;
    }
    unsigned rank;
    asm("mov.u32 %0, %%cluster_ctarank;" : "=r"(rank));
    const int dir = cid >> 2, batch = cid & 3;
    const int ct = (int)rank * 256 + tid;
    const int half = ct & 1, p = ct >> 1, gate = p & 3, d = p >> 2;
    const int gbase = (tid & 31) & ~7;
    const int lane7 = tid & 7;
    const bool prod = (tid & 7) == 0;
    const int dslot = (d < 128) ? d : d + 4;
    const float* whh = dir ? whh_b : whh_f;
    ulonglong2 w2[32];
    const ulonglong2* wp = (const ulonglong2*)(whh + ((size_t)(gate * 256 + d)) * 256 + half * 128);
#pragma unroll
    for (int i = 0; i < 32; i++) w2[i] = wp[i];
    for (int j = tid; j < 264; j += 256) hb[0][j] = 0.f;
    const float* preB = pre + ((size_t)dir * 512 + batch * 128) * 1024 + gate * 256 + d;
    float* ctxB = ctx + ((size_t)batch * 128) * 512 + dir * 256 + d;
    ushortt* cbB = ctxb + ((size_t)batch * 128) * 512 + dir * 256 + d;
    uint32_t la0 = smem_u32(&hb[0][dslot]);
    uint32_t la1 = smem_u32(&hb[1][dslot]);
    asm volatile("barrier.cluster.arrive.aligned;" ::: "memory");
    float preCur = preB[(size_t)(dir ? 127 : 0) * 1024];
    float cc = 0.f;
    for (int s = 0; s < 128; s++) {
        asm volatile("barrier.cluster.wait.aligned;" ::: "memory");
        const ulonglong2* hp = (const ulonglong2*)(&hb[s & 1][half ? 132 : 0]);
        unsigned long long a0 = 0ull, a1 = 0ull, a2 = 0ull, a3 = 0ull;
#pragma unroll
        for (int i = 0; i < 32; i += 2) {
            ulonglong2 h0 = hp[i], h1 = hp[i + 1];
            FMA2(a0, w2[i].x, h0.x);
            FMA2(a1, w2[i].y, h0.y);
            FMA2(a2, w2[i + 1].x, h1.x);
            FMA2(a3, w2[i + 1].y, h1.y);
        }
        float x0, x1, y0, y1, z0, z1, u0, u1;
        asm("mov.b64 {%0, %1}, %2;" : "=f"(x0), "=f"(x1) : "l"(a0));
        asm("mov.b64 {%0, %1}, %2;" : "=f"(y0), "=f"(y1) : "l"(a1));
        asm("mov.b64 {%0, %1}, %2;" : "=f"(z0), "=f"(z1) : "l"(a2));
        asm("mov.b64 {%0, %1}, %2;" : "=f"(u0), "=f"(u1) : "l"(a3));
        float acc = ((x0 + x1) + (y0 + y1)) + ((z0 + z1) + (u0 + u1));
        acc += __shfl_xor_sync(0xffffffffu, acc, 1);
        float gv = acc + preCur;
        float act = (gate == 2) ? ftanh(gv) : fsig(gv);
        float aI = __shfl_sync(0xffffffffu, act, gbase);
        float aF = __shfl_sync(0xffffffffu, act, gbase + 2);
        float aG = __shfl_sync(0xffffffffu, act, gbase + 4);
        float aO = __shfl_sync(0xffffffffu, act, gbase + 6);
        float hv = 0.f;
        if (prod) {
            cc = aF * cc + aI * aG;
            hv = aO * ftanh(cc);
        }
        hv = __shfl_sync(0xffffffffu, hv, gbase);
        if (s < 127) {
            uint32_t la = ((s + 1) & 1) ? la1 : la0;
            uint32_t ra;
            asm("mapa.shared::cluster.u32 %0, %1, %2;" : "=r"(ra) : "r"(la), "r"(lane7));
            asm volatile("st.shared::cluster.f32 [%0], %1;" :: "r"(ra), "f"(hv));
        }
        asm volatile("barrier.cluster.arrive.aligned;" ::: "memory");
        int time = dir ? (127 - s) : s;
        if (prod) {
            ctxB[(size_t)time * 512] = hv;
            ushortt hh, ll;
            bsplit(hv, hh, ll);
            cbB[(size_t)time * 512] = hh;
            cbB[(size_t)(512 * 512) + (size_t)time * 512] = ll;
        }
        if (s < 127) preCur = preB[(size_t)(dir ? (126 - s) : (s + 1)) * 1024];
    }
    asm volatile("barrier.cluster.wait.aligned;" ::: "memory");
}

// ---- attention + residual, fused with hop-0 F/G classifier dots ----
__global__ __launch_bounds__(256)
void attn_kernel(const float* __restrict__ q, const float* __restrict__ k,
                 const float* __restrict__ ctx, float* __restrict__ ctx2,
                 const float* __restrict__ cls_w, const float* __restrict__ cls_b,
                 float* __restrict__ F, float* __restrict__ G) {
    int row = blockIdx.x, b = row >> 7, tid = threadIdx.x;
    __shared__ float qsh[512], sc[128], red[128];
    for (int j = tid; j < 512; j += 256) qsh[j] = q[(size_t)row * 512 + j];
    __syncthreads();
    {
        int m = tid >> 1, half = tid & 1;
        const float* kr = k + ((size_t)(b * 128 + m)) * 512 + half * 256;
        const float* qh = qsh + half * 256;
        float s = 0.f;
#pragma unroll 8
        for (int j = 0; j < 256; j++) s = fmaf(qh[j], kr[j], s);
        s += __shfl_xor_sync(0xffffffffu, s, 1);
        if (!half) sc[m] = s;
    }
    __syncthreads();
    if (tid < 128) red[tid] = sc[tid];
    __syncthreads();
    for (int s = 64; s > 0; s >>= 1) {
        if (tid < s) red[tid] = fmaxf(red[tid], red[tid + s]);
        __syncthreads();
    }
    float mx = red[0];
    __syncthreads();
    if (tid < 128) { float e = __expf(sc[tid] - mx); sc[tid] = e; red[tid] = e; }
    __syncthreads();
    for (int s = 64; s > 0; s >>= 1) {
        if (tid < s) red[tid] += red[tid + s];
        __syncthreads();
    }
    float inv = 1.f / red[0];
    __syncthreads();
    int c0 = tid * 2;
    float o0 = 0.f, o1 = 0.f;
    for (int m = 0; m < 128; m++) {
        float a = sc[m] * inv;
        float2 cv = *(const float2*)(ctx + ((size_t)(b * 128 + m)) * 512 + c0);
        o0 = fmaf(a, cv.x, o0);
        o1 = fmaf(a, cv.y, o1);
    }
    float2 bs = *(const float2*)(ctx + (size_t)row * 512 + c0);
    float r0 = o0 + bs.x, r1 = o1 + bs.y;
    *(float2*)(ctx2 + (size_t)row * 512 + c0) = make_float2(r0, r1);
    __syncthreads();
    qsh[c0] = r0;
    qsh[c0 + 1] = r1;
    __syncthreads();
    int w = tid >> 5, L2 = tid & 31;
    for (int c = w; c < 12; c += 8) {
        const float* wv = cls_w + (size_t)(c % 6) * 1024 + (c >= 6 ? 512 : 0);
        float a = 0.f;
        for (int i = L2; i < 128; i += 32) {
            float4 x = *(const float4*)(qsh + i * 4);
            float4 ww = *(const float4*)(wv + i * 4);
            a += x.x * ww.x + x.y * ww.y + x.z * ww.z + x.w * ww.w;
        }
#pragma unroll
        for (int sft = 16; sft > 0; sft >>= 1) a += __shfl_xor_sync(0xffffffffu, a, sft);
        if (L2 == 0) {
            if (c < 6) F[(size_t)row * Cn + c] = a + cls_b[c];
            else G[(size_t)row * Cn + (c - 6)] = a;
        }
    }
}

__global__ __launch_bounds__(256)
void smallmm3(const float* __restrict__ A0, const float* __restrict__ A1, int lda, int K,
              const float* __restrict__ W, int ldw, int off0, int off1,
              const float* __restrict__ bias, float* __restrict__ C0, float* __restrict__ C1) {
    int z = blockIdx.z;
    int w = threadIdx.x >> 5, L = threadIdx.x & 31;
    int row = blockIdx.x * 8 + w;
    const float* A = (z ? A1 : A0) + (size_t)row * lda;
    int off = z ? off1 : off0;
    float acc[Cn] = {0, 0, 0, 0, 0, 0};
    for (int i = L; i * 4 < K; i += 32) {
        float4 a = *(const float4*)(A + i * 4);
#pragma unroll
        for (int c = 0; c < Cn; c++) {
            float4 wv = *(const float4*)(W + (size_t)c * ldw + off + i * 4);
            acc[c] += a.x * wv.x + a.y * wv.y + a.z * wv.z + a.w * wv.w;
        }
    }
#pragma unroll
    for (int sft = 16; sft > 0; sft >>= 1)
#pragma unroll
        for (int c = 0; c < Cn; c++) acc[c] += __shfl_xor_sync(0xffffffffu, acc[c], sft);
    if (L == 0) {
        float* C = (z ? C1 : C0) + (size_t)row * Cn;
#pragma unroll
        for (int c = 0; c < Cn; c++) C[c] = acc[c] + ((z == 0 && bias) ? bias[c] : 0.f);
    }
}

static __device__ __forceinline__ void row_lm(const float* F, const float* G,
                                              int b, int l, float* lmsh) {
    int tid = threadIdx.x;
    if (tid < 192) {
        int c = tid >> 5, lane = tid & 31;
        const float* Fb = F + (size_t)(b * Ln) * Cn + c;
        const float* Gb = G + (size_t)(b * Ln) * Cn + c;
        float pf = -3.0e38f, sg = -3.0e38f;
        for (int l2 = lane; l2 <= l; l2 += 32) pf = fmaxf(pf, Fb[l2 * Cn]);
        for (int l2 = l + lane; l2 < Ln; l2 += 32) sg = fmaxf(sg, Gb[l2 * Cn]);
#pragma unroll
        for (int sft = 16; sft > 0; sft >>= 1) {
            pf = fmaxf(pf, __shfl_xor_sync(0xffffffffu, pf, sft));
            sg = fmaxf(sg, __shfl_xor_sync(0xffffffffu, sg, sft));
        }
        if (lane == 0) {
            float v1 = Gb[l * Cn] + pf;
            if (l < Ln - 1) v1 = fmaxf(v1, 0.f);
            float v2 = Fb[l * Cn] + sg;
            if (l > 0) v2 = fmaxf(v2, 0.f);
            lmsh[c] = fmaxf(v1, v2);
        }
    }
    __syncthreads();
}

__global__ __launch_bounds__(256)
void build_ab1(const float* __restrict__ ctx2, const float* __restrict__ F,
               const float* __restrict__ G,
               ushortt* __restrict__ AbU, ushortt* __restrict__ AbV) {
    int row = blockIdx.x;
    __shared__ float lmsh[8];
    row_lm(F, G, row >> 7, row & 127, lmsh);
    const int n = BL * KC1P;
    for (int j = threadIdx.x; j < KC1P; j += blockDim.x) {
        float u = 0.f, v = 0.f;
        if (j < 512) { u = v = ctx2[(size_t)row * 512 + j]; }
        else if (j < 518) { u = v = lmsh[j - 512]; }
        else if (j < 524) { u = F[(size_t)row * Cn + (j - 518)]; v = G[(size_t)row * Cn + (j - 518)]; }
        ushortt h, l;
        int idx = row * KC1P + j;
        bsplit(u, h, l); AbU[idx] = h; AbU[n + idx] = l;
        bsplit(v, h, l); AbV[idx] = h; AbV[n + idx] = l;
    }
}

__global__ __launch_bounds__(256)
void build_bar(const float* __restrict__ U, const float* __restrict__ V,
               const float* __restrict__ F, const float* __restrict__ G,
               ushortt* __restrict__ Ub, ushortt* __restrict__ Vb) {
    int row = blockIdx.x;
    __shared__ float lmsh[8];
    row_lm(F, G, row >> 7, row & 127, lmsh);
    const int n = BL * KFP;
    for (int j = threadIdx.x; j < KFP; j += blockDim.x) {
        float u = 0.f, v = 0.f;
        if (j < 1024) { u = U[(size_t)row * 1024 + j]; v = V[(size_t)row * 1024 + j]; }
        else if (j < 1030) { u = lmsh[j - 1024]; }
        else if (j < 1036) { v = lmsh[j - 1030]; }
        else if (j < 1042) { u = F[(size_t)row * Cn + (j - 1036)]; v = G[(size_t)row * Cn + (j - 1036)]; }
        ushortt h, l;
        int idx = row * KFP + j;
        bsplit(u, h, l); Ub[idx] = h; Ub[n + idx] = l;
        bsplit(v, h, l); Vb[idx] = h; Vb[n + idx] = l;
    }
}

__global__ void final_kernel(const float* __restrict__ F, const float* __restrict__ G, float* __restrict__ out) {
    int idx = blockIdx.x * blockDim.x + threadIdx.x;
    if (idx >= Bn * Ln * Ln * Cn) return;
    int c = idx % Cn, j = (idx / Cn) % Ln, i = (idx / (Cn * Ln)) % Ln, b = idx / (Cn * Ln * Ln);
    out[idx] = F[((size_t)(b * Ln + i)) * Cn + c] + G[((size_t)(b * Ln + j)) * Cn + c];
}

extern "C" void kernel_launch(void* const* d_in, const int* in_sizes, int n_in,
                              void* d_out, int out_size) {
    (void)in_sizes; (void)n_in; (void)out_size;
    const int* toks = (const int*)d_in[0];
    const float* mask = (const float*)d_in[2];
    const float* gen = (const float*)d_in[3];
    const float* dom = (const float*)d_in[4];
    const float* wih_f = (const float*)d_in[5];
    const float* whh_f = (const float*)d_in[6];
    const float* bih_f = (const float*)d_in[7];
    const float* bhh_f = (const float*)d_in[8];
    const float* wih_b = (const float*)d_in[9];
    const float* whh_b = (const float*)d_in[10];
    const float* bih_b = (const float*)d_in[11];
    const float* bhh_b = (const float*)d_in[12];
    const float* wq = (const float*)d_in[13];
    const float* bq = (const float*)d_in[14];
    const float* wk = (const float*)d_in[15];
    const float* bk = (const float*)d_in[16];
    const float* feat_w = (const float*)d_in[17];
    const float* feat_b = (const float*)d_in[18];
    const float* cls_w = (const float*)d_in[19];
    const float* cls_b = (const float*)d_in[20];
    float* out = (float*)d_out;

    float* S = nullptr;
    cudaGetSymbolAddress((void**)&S, d_scratch);
    ushortt* EB   = (ushortt*)(S + O_EB);
    ushortt* WIHF = (ushortt*)(S + O_WIHF);
    ushortt* WIHB = (ushortt*)(S + O_WIHB);
    float* pre  = S + O_PRE;
    float* ctx  = S + O_CTX;
    ushortt* CTXB = (ushortt*)(S + O_CTXB);
    ushortt* WQB  = (ushortt*)(S + O_WQB);
    ushortt* WKB  = (ushortt*)(S + O_WKB);
    float* qb = S + O_Q;
    float* kb = S + O_K;
    float* ctx2 = S + O_CTX2;
    float* F = S + O_F;   float* G = S + O_G;
    float* F2 = S + O_F2; float* G2 = S + O_G2;
    float* U = S + O_U;   float* V = S + O_V;
    float* U2 = S + O_U2; float* V2 = S + O_V2;
    ushortt* ABUB = (ushortt*)(S + O_ABUB);
    ushortt* ABVB = (ushortt*)(S + O_ABVB);
    ushortt* WUCB = (ushortt*)(S + O_WUCB);
    ushortt* WVCB = (ushortt*)(S + O_WVCB);
    ushortt* WPB  = (ushortt*)(S + O_WPB);
    ushortt* UBB  = (ushortt*)(S + O_UBB);
    ushortt* VBB  = (ushortt*)(S + O_VBB);

    prep_w<<<(N_PREP + 255) / 256, 256>>>(toks, mask, gen, dom, wih_f, wih_b, wq, wk,
                                          EB, WIHF, WIHB, WQB, WKB);
    bgemm<<<dim3(16, 8, 2), 128>>>(EB, EB, 400, WIHF, WIHB, 400,
                                   bih_f, bhh_f, bih_b, bhh_b,
                                   pre, pre + (size_t)BL * 1024, 1024, 400);
    lstm_cluster<<<128, 256>>>(whh_f, whh_b, pre, ctx, CTXB, feat_w, WUCB, WVCB, WPB);
    bgemm<<<dim3(8, 8, 2), 128>>>(CTXB, CTXB, 512, WQB, WKB, 512,
                                  bq, nullptr, bk, nullptr, qb, kb, 512, 512);
    attn_kernel<<<BL, 256>>>(qb, kb, ctx, ctx2, cls_w, cls_b, F, G);
    build_ab1<<<BL, 256>>>(ctx2, F, G, ABUB, ABVB);
    bgemm<<<dim3(16, 8, 2), 128>>>(ABUB, ABVB, KC1P, WUCB, WVCB, KC1P,
                                   feat_b, nullptr, nullptr, nullptr, U, V, 1024, KC1P);
    smallmm3<<<dim3(BL / 8, 1, 2), 256>>>(U, V, 1024, 1024, cls_w, 1024, 0, 0, cls_b, F2, G2);
    build_bar<<<BL, 256>>>(U, V, F2, G2, UBB, VBB);
    bgemm<<<dim3(16, 8, 2), 128>>>(UBB, VBB, KFP, WPB, WPB, KFP,
                                   feat_b, nullptr, nullptr, nullptr, U2, V2, 1024, KFP);
    smallmm3<<<dim3(BL / 8, 1, 2), 256>>>(U2, V2, 1024, 1024, cls_w, 1024, 0, 0, cls_b, F, G);
    final_kernel<<<1536, 256>>>(F, G, out);
}